// round 14
// baseline (speedup 1.0000x reference)
#include <cuda_runtime.h>
#include <cuda_bf16.h>
#include <math.h>
#include <stdint.h>

#define NC 10

// ---------------- scratch (static device arrays; no runtime allocation) ----------------
__device__ __nv_bfloat16 g_hh[52428800];  // [512 b][20 y][20 x][256 c] conv1 out, bf16 hi
__device__ __nv_bfloat16 g_hl[52428800];  // same, bf16 lo (residual)
__device__ __nv_bfloat16 g_wh[5308416];   // [81 dydx][256 ci][256 oc] weights hi
__device__ __nv_bfloat16 g_wl[5308416];   // weights lo
__device__ float g_rw2[1474560];          // [10 c][128 io][1152 r] transposed route_w
__device__ float g_u[4718592];            // [512][1152][8] primary capsules (squashed)
__device__ float g_caps[81920];           // [512][10][16]
__device__ int   g_am[512];               // argmax class per image
__device__ float g_c16[8192];             // [512][16] winning capsule
__device__ float g_d1[262144];            // [512][512]
__device__ float g_d2[524288];            // [512][1024]

// ---------------- PTX helpers (all baseline sm_80+; no arch-'a' features) ----------------
__device__ __forceinline__ void ffma2(float2& c, const float2 a, const float2 b) {
    asm("fma.rn.f32x2 %0, %1, %2, %0;"
        : "+l"(reinterpret_cast<unsigned long long&>(c))
        : "l"(reinterpret_cast<const unsigned long long&>(a)),
          "l"(reinterpret_cast<const unsigned long long&>(b)));
}
__device__ __forceinline__ void cp16(uint32_t d, const void* s) {
    asm volatile("cp.async.cg.shared.global [%0], [%1], 16;" :: "r"(d), "l"(s));
}
__device__ __forceinline__ void cp_commit() { asm volatile("cp.async.commit_group;"); }
__device__ __forceinline__ void cp_wait0()  { asm volatile("cp.async.wait_group 0;" ::: "memory"); }

__device__ __forceinline__ void ldsm4(uint32_t* r, uint32_t addr) {
    asm volatile("ldmatrix.sync.aligned.m8n8.x4.shared.b16 {%0,%1,%2,%3}, [%4];"
        : "=r"(r[0]), "=r"(r[1]), "=r"(r[2]), "=r"(r[3]) : "r"(addr));
}
__device__ __forceinline__ void ldsm4t(uint32_t* r, uint32_t addr) {
    asm volatile("ldmatrix.sync.aligned.m8n8.x4.trans.shared.b16 {%0,%1,%2,%3}, [%4];"
        : "=r"(r[0]), "=r"(r[1]), "=r"(r[2]), "=r"(r[3]) : "r"(addr));
}
__device__ __forceinline__ void mma16816(float* c, const uint32_t* a, const uint32_t* b) {
    asm volatile("mma.sync.aligned.m16n8k16.row.col.f32.bf16.bf16.f32 "
        "{%0,%1,%2,%3}, {%4,%5,%6,%7}, {%8,%9}, {%0,%1,%2,%3};"
        : "+f"(c[0]), "+f"(c[1]), "+f"(c[2]), "+f"(c[3])
        : "r"(a[0]), "r"(a[1]), "r"(a[2]), "r"(a[3]), "r"(b[0]), "r"(b[1]));
}

// ---------------- weight prep: prim_w -> [dydx][ci][oc] hi/lo bf16 ----------------
__global__ __launch_bounds__(256) void prep_w_kernel(const float* __restrict__ pw) {
    int idx = blockIdx.x * 256 + threadIdx.x;   // 65536 = ci*256 + oc
    int ci = idx >> 8, oc = idx & 255;
    const float* src = pw + (size_t)(oc * 256 + ci) * 81;
#pragma unroll 3
    for (int k = 0; k < 81; k++) {
        float w = src[k];
        __nv_bfloat16 hi = __float2bfloat16(w);
        __nv_bfloat16 lo = __float2bfloat16(w - __bfloat162float(hi));
        size_t o = ((size_t)k * 256 + ci) * 256 + oc;
        g_wh[o] = hi;
        g_wl[o] = lo;
    }
}

// ---------------- route_w transpose: [c][r][i][o] -> [c][io][r] ----------------
__global__ __launch_bounds__(256) void prep_rw_kernel(const float* __restrict__ rw) {
    __shared__ float tile[32][33];
    int rb = blockIdx.x, iob = blockIdx.y, c = blockIdx.z;
    int tx = threadIdx.x & 31, ty = threadIdx.x >> 5;   // ty 0..7
#pragma unroll
    for (int k = 0; k < 4; k++) {
        int r = rb * 32 + ty * 4 + k;
        tile[ty * 4 + k][tx] = rw[((size_t)c * 1152 + r) * 128 + iob * 32 + tx];
    }
    __syncthreads();
#pragma unroll
    for (int k = 0; k < 4; k++) {
        int io = iob * 32 + ty * 4 + k;
        g_rw2[((size_t)c * 128 + io) * 1152 + rb * 32 + tx] = tile[tx][ty * 4 + k];
    }
}

// ---------------- conv1: 2 images/block via FFMA2 -> relu -> NHWC bf16 hi/lo ----------------
__global__ __launch_bounds__(640) void conv1_kernel(const float* __restrict__ x,
                                                    const float* __restrict__ w,
                                                    const float* __restrict__ bias) {
    __shared__ __align__(16) float2 img2[784];
    __shared__ float ws[2592];
    __shared__ float bs[32];
    int bp = blockIdx.y, ocg = blockIdx.x, t = threadIdx.x;
    const float* x0 = x + (size_t)(bp * 2) * 784;
    const float* x1 = x0 + 784;
    for (int i = t; i < 784; i += 640) img2[i] = make_float2(x0[i], x1[i]);
    for (int i = t; i < 2592; i += 640) ws[i] = w[(size_t)ocg * 2592 + i];
    if (t < 32) bs[t] = bias[ocg * 32 + t];
    __syncthreads();
    int oc = t & 31, y = t >> 5;
    float2 acc[20];
#pragma unroll
    for (int i = 0; i < 20; i++) acc[i] = make_float2(0.f, 0.f);
    for (int dy = 0; dy < 9; dy++) {
        const float2* rp = img2 + (y + dy) * 28;
        const float* wrow = ws + oc * 81 + dy * 9;
#pragma unroll
        for (int q = 0; q < 4; q++) {          // xo quarters of 5, cols q*5 .. q*5+12
            float2 r[14];
#pragma unroll
            for (int i = 0; i < 14; i++) r[i] = rp[q * 5 + i];
#pragma unroll
            for (int dx = 0; dx < 9; dx++) {
                float wv = wrow[dx];
                float2 w2 = make_float2(wv, wv);
#pragma unroll
                for (int xo = 0; xo < 5; xo++)
                    ffma2(acc[q * 5 + xo], w2, r[xo + dx]);
            }
        }
    }
    float bv = bs[oc];
    size_t base0 = (((size_t)(bp * 2) * 20 + y) * 20) * 256 + ocg * 32 + oc;
    size_t base1 = base0 + (size_t)400 * 256;
#pragma unroll
    for (int i = 0; i < 20; i++) {
        float v0 = fmaxf(acc[i].x + bv, 0.f);
        float v1 = fmaxf(acc[i].y + bv, 0.f);
        __nv_bfloat16 h0 = __float2bfloat16(v0);
        __nv_bfloat16 h1 = __float2bfloat16(v1);
        g_hh[base0 + (size_t)i * 256] = h0;
        g_hl[base0 + (size_t)i * 256] = __float2bfloat16(v0 - __bfloat162float(h0));
        g_hh[base1 + (size_t)i * 256] = h1;
        g_hl[base1 + (size_t)i * 256] = __float2bfloat16(v1 - __bfloat162float(h1));
    }
}

// ---------------- conv2 via mma.sync bf16 (hi/lo, 3 passes) + fused bias/squash ----------------
// 512 thr / 16 warps, warp w owns N=16 (oc w*16..), 9 m-tiles in 3 groups of 3.
// Pass-major MMA order within each group: same-accumulator revisit distance 6 MMAs
// (vs 2 before) -> no tensor accumulate-latency stalls. Per-acc order unchanged (hh,hl,lh).
#define C2_AHI   0u
#define C2_ALO   20736u
#define C2_BHI   41472u
#define C2_BLO   75264u
#define C2_BUFSZ 109056u
#define C2_STEPS 324

__global__ __launch_bounds__(512, 1) void conv2_mma_kernel(const float* __restrict__ bias) {
    extern __shared__ __align__(16) char smc[];
    uint32_t smb = (uint32_t)__cvta_generic_to_shared(smc);
    int t = threadIdx.x;
    int bq = blockIdx.x;
    int w = t >> 5, T = t & 31;

    // A staging descriptors
    uint32_t asrc[3], adst[3]; int an = 0;
#pragma unroll
    for (int i = 0; i < 3; i++) {
        int idx = t + i * 512;
        if (idx < 1152) {
            int row = idx >> 3, c = idx & 7;
            int img = row / 36, p = row - img * 36, oy = p / 6, ox = p - oy * 6;
            asrc[an] = (uint32_t)((((long)(bq * 4 + img) * 400 + (long)(2 * oy) * 20 + 2 * ox) * 256 + c * 8) * 2);
            adst[an] = (uint32_t)(row * 144 + c * 16);
            an++;
        }
    }
    // B staging: affine in i (idx += 512 -> row += 16)
    uint32_t bsrc0, bdst0;
    {
        int row = t >> 5, c = t & 31;
        bsrc0 = (uint32_t)((row * 256 + c * 8) * 2);   // += 8192 per i
        bdst0 = (uint32_t)(row * 528 + c * 16);        // += 8448 per i
    }
    const char* hh = (const char*)g_hh;
    const char* hl = (const char*)g_hl;
    const char* wh = (const char*)g_wh;
    const char* wl = (const char*)g_wl;

    // prologue: stage step 0 into buffer 0
    {
        uint32_t ba = smb;
        for (int i = 0; i < an; i++) {
            cp16(ba + C2_AHI + adst[i], hh + asrc[i]);
            cp16(ba + C2_ALO + adst[i], hl + asrc[i]);
        }
#pragma unroll
        for (int i = 0; i < 4; i++) {
            cp16(ba + C2_BHI + bdst0 + i * 8448u, wh + bsrc0 + i * 8192u);
            cp16(ba + C2_BLO + bdst0 + i * 8448u, wl + bsrc0 + i * 8192u);
        }
        cp_commit();
    }

    float acc[9][2][4];
#pragma unroll
    for (int m = 0; m < 9; m++)
#pragma unroll
        for (int n = 0; n < 2; n++)
#pragma unroll
            for (int i = 0; i < 4; i++) acc[m][n][i] = 0.f;

    uint32_t arow = (uint32_t)((T & 15) * 144 + ((T & 16) ? 16 : 0));
    uint32_t brow = (uint32_t)((T & 15) * 528 + w * 32 + ((T & 16) ? 16 : 0));

    for (int s = 0; s < C2_STEPS; s++) {
        cp_wait0();          // step-s data arrived
        __syncthreads();     // all warps done reading buf[(s+1)&1] (step s-1)
        if (s + 1 < C2_STEPS) {
            int s1 = s + 1, dydx = s1 >> 2, ci0 = (s1 & 3) * 64;
            int dy = dydx / 9, dx = dydx - dy * 9;
            uint32_t stepA = (uint32_t)(((dy * 20 + dx) * 256 + ci0) * 2);
            uint32_t stepB = (uint32_t)(((dydx * 256 + ci0) * 256) * 2);
            uint32_t ba = smb + (uint32_t)((s1 & 1) ? C2_BUFSZ : 0u);
            for (int i = 0; i < an; i++) {
                cp16(ba + C2_AHI + adst[i], hh + asrc[i] + stepA);
                cp16(ba + C2_ALO + adst[i], hl + asrc[i] + stepA);
            }
#pragma unroll
            for (int i = 0; i < 4; i++) {
                cp16(ba + C2_BHI + bdst0 + i * 8448u, wh + bsrc0 + stepB + i * 8192u);
                cp16(ba + C2_BLO + bdst0 + i * 8448u, wl + bsrc0 + stepB + i * 8192u);
            }
            cp_commit();
        }
        uint32_t base = smb + (uint32_t)((s & 1) ? C2_BUFSZ : 0u);
        uint32_t Ah = base + C2_AHI, Al = base + C2_ALO;
        uint32_t Bh = base + C2_BHI, Bl = base + C2_BLO;
#pragma unroll
        for (int kk = 0; kk < 4; kk++) {
            uint32_t bh[4], bl[4];
            uint32_t bo = (uint32_t)(kk * 16 * 528) + brow;
            ldsm4t(bh, Bh + bo);
            ldsm4t(bl, Bl + bo);
#pragma unroll
            for (int g = 0; g < 3; g++) {
                uint32_t ah[3][4], al[3][4];
#pragma unroll
                for (int m = 0; m < 3; m++) {
                    uint32_t ao = (uint32_t)(((g * 3 + m) * 16 * 144) + kk * 32) + arow;
                    ldsm4(ah[m], Ah + ao);
                    ldsm4(al[m], Al + ao);
                }
                // pass hh
#pragma unroll
                for (int m = 0; m < 3; m++) {
                    mma16816(acc[g * 3 + m][0], ah[m], bh);
                    mma16816(acc[g * 3 + m][1], ah[m], bh + 2);
                }
                // pass hl
#pragma unroll
                for (int m = 0; m < 3; m++) {
                    mma16816(acc[g * 3 + m][0], ah[m], bl);
                    mma16816(acc[g * 3 + m][1], ah[m], bl + 2);
                }
                // pass lh
#pragma unroll
                for (int m = 0; m < 3; m++) {
                    mma16816(acc[g * 3 + m][0], al[m], bh);
                    mma16816(acc[g * 3 + m][1], al[m], bh + 2);
                }
            }
        }
    }

    // ---- fused epilogue: bias add -> smem [img][p][m][9] -> squash -> g_u ----
    __syncthreads();                       // everyone done with step 323's buffer
    float* S = (float*)smc;                // 4*36*32*9 floats = 165888 B
    int gid = T >> 2, tig = T & 3;
#pragma unroll
    for (int nt = 0; nt < 2; nt++) {
        int oc0 = w * 16 + nt * 8 + tig * 2;
        int oc1 = oc0 + 1;
        float bv0 = bias[oc0], bv1 = bias[oc1];
        int off0 = (oc0 & 31) * 9 + (oc0 >> 5);
        int off1 = (oc1 & 31) * 9 + (oc1 >> 5);
#pragma unroll
        for (int mt = 0; mt < 9; mt++) {
#pragma unroll
            for (int h = 0; h < 2; h++) {
                int row = mt * 16 + gid + h * 8;
                int img = row / 36, p = row - img * 36;
                int base = (img * 36 + p) * 288;   // 32*9
                S[base + off0] = acc[mt][nt][h * 2 + 0] + bv0;
                S[base + off1] = acc[mt][nt][h * 2 + 1] + bv1;
            }
        }
    }
    __syncthreads();
#pragma unroll
    for (int k = 0; k < 9; k++) {
        int c = t + k * 512;                // 4608 capsules: c = img*1152 + r, r = m*36+p
        int img = c / 1152;
        int r = c - img * 1152;
        int m = r / 36, p = r - m * 36;
        const float* sp = S + (img * 36 + p) * 288 + m * 9;
        float v0 = sp[0], v1 = sp[1], v2 = sp[2], v3 = sp[3];
        float v4 = sp[4], v5 = sp[5], v6 = sp[6], v7 = sp[7];
        float sq = v0*v0 + v1*v1 + v2*v2 + v3*v3 + v4*v4 + v5*v5 + v6*v6 + v7*v7;
        float sc = sq / ((1.f + sq) * sqrtf(sq));
        float4* dst = (float4*)(g_u + ((size_t)(bq * 4 + img) * 1152 + r) * 8);
        dst[0] = make_float4(v0 * sc, v1 * sc, v2 * sc, v3 * sc);
        dst[1] = make_float4(v4 * sc, v5 * sc, v6 * sc, v7 * sc);
    }
}

// ---------------- routing: block = (class, image), 288 threads x 4 consecutive routes ----------
// route_w loads are float4 (transposed layout), u loads are float4. 2 CTAs/SM. (R11 config)
__global__ __launch_bounds__(288, 2) void routing_kernel() {
    __shared__ float red[9][17];
    __shared__ float mred[9];
    int c = blockIdx.x, b = blockIdx.y, t = threadIdx.x;
    int lane = t & 31, wid = t >> 5;
    const float4* w4 = (const float4*)(g_rw2 + (size_t)c * 147456);
    const float4* up = (const float4*)(g_u + (size_t)b * 9216 + (size_t)t * 32);

    // u values for 4 consecutive routes (4t .. 4t+3)
    float uu[4][8];
#pragma unroll
    for (int j = 0; j < 4; j++) {
        float4 a = up[j * 2], bb = up[j * 2 + 1];
        uu[j][0] = a.x; uu[j][1] = a.y; uu[j][2] = a.z; uu[j][3] = a.w;
        uu[j][4] = bb.x; uu[j][5] = bb.y; uu[j][6] = bb.z; uu[j][7] = bb.w;
    }

    float pr[4][16];
#pragma unroll
    for (int j = 0; j < 4; j++)
#pragma unroll
        for (int o = 0; o < 16; o++) pr[j][o] = 0.f;

#pragma unroll
    for (int i = 0; i < 8; i++) {
#pragma unroll
        for (int o = 0; o < 16; o++) {
            float4 wv = w4[(size_t)(i * 16 + o) * 288 + t];
            pr[0][o] = fmaf(uu[0][i], wv.x, pr[0][o]);
            pr[1][o] = fmaf(uu[1][i], wv.y, pr[1][o]);
            pr[2][o] = fmaf(uu[2][i], wv.z, pr[2][o]);
            pr[3][o] = fmaf(uu[3][i], wv.w, pr[3][o]);
        }
    }

    float lg[4] = {0.f, 0.f, 0.f, 0.f};
    float s[16];
    for (int it = 0; it < 3; it++) {
        // block max of logits
        float mx = fmaxf(fmaxf(lg[0], lg[1]), fmaxf(lg[2], lg[3]));
#pragma unroll
        for (int off = 16; off; off >>= 1) mx = fmaxf(mx, __shfl_xor_sync(0xffffffffu, mx, off));
        if (lane == 0) mred[wid] = mx;
        __syncthreads();
        float M = mred[0];
#pragma unroll
        for (int ww = 1; ww < 9; ww++) M = fmaxf(M, mred[ww]);

        // weighted sums
#pragma unroll
        for (int o = 0; o < 16; o++) s[o] = 0.f;
        float z = 0.f;
#pragma unroll
        for (int j = 0; j < 4; j++) {
            float e = expf(lg[j] - M);
            z += e;
#pragma unroll
            for (int o = 0; o < 16; o++) s[o] = fmaf(e, pr[j][o], s[o]);
        }
#pragma unroll
        for (int off = 16; off; off >>= 1) {
            z += __shfl_xor_sync(0xffffffffu, z, off);
#pragma unroll
            for (int o = 0; o < 16; o++) s[o] += __shfl_xor_sync(0xffffffffu, s[o], off);
        }
        if (lane == 0) {
#pragma unroll
            for (int o = 0; o < 16; o++) red[wid][o] = s[o];
            red[wid][16] = z;
        }
        __syncthreads();
        float Z = 0.f;
#pragma unroll
        for (int o = 0; o < 16; o++) s[o] = 0.f;
#pragma unroll
        for (int ww = 0; ww < 9; ww++) {
            Z += red[ww][16];
#pragma unroll
            for (int o = 0; o < 16; o++) s[o] += red[ww][o];
        }
        float q = 0.f;
#pragma unroll
        for (int o = 0; o < 16; o++) { s[o] /= Z; q = fmaf(s[o], s[o], q); }
        float sc = q / ((1.f + q) * sqrtf(q));
#pragma unroll
        for (int o = 0; o < 16; o++) s[o] *= sc;
        if (it < 2) {
#pragma unroll
            for (int j = 0; j < 4; j++) {
                float d = 0.f;
#pragma unroll
                for (int o = 0; o < 16; o++) d = fmaf(pr[j][o], s[o], d);
                lg[j] += d;
            }
        }
        __syncthreads();   // protect red/mred before next iteration's writes
    }
    if (t == 0) {
        float* cp = g_caps + ((size_t)b * NC + c) * 16;
#pragma unroll
        for (int o = 0; o < 16; o++) cp[o] = s[o];
    }
}

// ---------------- classes softmax + argmax -> compact decoder input ----------------
__global__ void classes_kernel(float* __restrict__ out_classes) {
    int b = blockIdx.x, lane = threadIdx.x;  // 32 threads
    float n2 = 0.f;
    if (lane < NC) {
        const float* cp = g_caps + ((size_t)b * NC + lane) * 16;
#pragma unroll
        for (int o = 0; o < 16; o++) n2 = fmaf(cp[o], cp[o], n2);
    }
    float nrm = (lane < NC) ? sqrtf(n2) : -3.0e38f;
    float mx = nrm;
#pragma unroll
    for (int off = 16; off; off >>= 1) mx = fmaxf(mx, __shfl_xor_sync(0xffffffffu, mx, off));
    float e = (lane < NC) ? expf(nrm - mx) : 0.f;
    float zz = e;
#pragma unroll
    for (int off = 16; off; off >>= 1) zz += __shfl_xor_sync(0xffffffffu, zz, off);
    if (lane < NC) out_classes[b * NC + lane] = e / zz;
    unsigned msk = __ballot_sync(0xffffffffu, nrm == mx);
    int am = __ffs(msk) - 1;   // first (lowest-index) max, matches jnp.argmax
    const float* ap = g_caps + ((size_t)b * NC + am) * 16;
    if (lane < 16) g_c16[b * 16 + lane] = ap[lane];
    if (lane == 0) g_am[b] = am;
}

// ---------------- sparse decoder layer 1: d1 = relu(W1[:, am*16 : am*16+16] @ c16 + b1) ------
__global__ __launch_bounds__(256) void gemm1s_kernel(const float* __restrict__ W1,
                                                     const float* __restrict__ b1v,
                                                     float* __restrict__ d1) {
    int idx = blockIdx.x * 256 + threadIdx.x;   // 512*512 outputs
    int row = idx >> 9, n = idx & 511;
    int am = g_am[row];
    const float4* wp = (const float4*)(W1 + (size_t)n * 160 + am * 16);
    const float4* cp = (const float4*)(g_c16 + row * 16);
    float acc = 0.f;
#pragma unroll
    for (int q = 0; q < 4; q++) {
        float4 wv = wp[q], cv = cp[q];
        acc = fmaf(wv.x, cv.x, acc);
        acc = fmaf(wv.y, cv.y, acc);
        acc = fmaf(wv.z, cv.z, acc);
        acc = fmaf(wv.w, cv.w, acc);
    }
    d1[idx] = fmaxf(acc + b1v[n], 0.f);
}

// ---------------- decoder GEMM: C[512,N] = act(A[512,K] @ W[N,K]^T + bias) ----------------
__global__ __launch_bounds__(256) void gemm_kernel(const float* __restrict__ A,
                                                   const float* __restrict__ W,
                                                   const float* __restrict__ bias,
                                                   float* __restrict__ C,
                                                   int N, int K, int act) {
    __shared__ float As[64][33];
    __shared__ float Bs[64][33];
    int tx = threadIdx.x & 15, ty = threadIdx.x >> 4;
    int m0 = blockIdx.y * 64, n0 = blockIdx.x * 64;
    float acc[4][4];
#pragma unroll
    for (int i = 0; i < 4; i++)
#pragma unroll
        for (int j = 0; j < 4; j++) acc[i][j] = 0.f;
    for (int k0 = 0; k0 < K; k0 += 32) {
        __syncthreads();
        for (int idx = threadIdx.x; idx < 2048; idx += 256) {
            int mm = idx >> 5, kk = idx & 31;
            As[mm][kk] = A[(size_t)(m0 + mm) * K + k0 + kk];
            Bs[mm][kk] = (n0 + mm < N) ? W[(size_t)(n0 + mm) * K + k0 + kk] : 0.f;
        }
        __syncthreads();
#pragma unroll
        for (int kk = 0; kk < 32; kk++) {
            float a[4], bb[4];
#pragma unroll
            for (int i = 0; i < 4; i++) a[i] = As[ty * 4 + i][kk];
#pragma unroll
            for (int j = 0; j < 4; j++) bb[j] = Bs[tx * 4 + j][kk];
#pragma unroll
            for (int i = 0; i < 4; i++)
#pragma unroll
                for (int j = 0; j < 4; j++) acc[i][j] = fmaf(a[i], bb[j], acc[i][j]);
        }
    }
#pragma unroll
    for (int i = 0; i < 4; i++) {
        int cm = m0 + ty * 4 + i;
#pragma unroll
        for (int j = 0; j < 4; j++) {
            int cn = n0 + tx * 4 + j;
            if (cn < N) {
                float val = acc[i][j] + bias[cn];
                val = act ? (1.f / (1.f + expf(-val))) : fmaxf(val, 0.f);
                C[(size_t)cm * N + cn] = val;
            }
        }
    }
}

extern "C" void kernel_launch(void* const* d_in, const int* in_sizes, int n_in,
                              void* d_out, int out_size) {
    const float* x   = (const float*)d_in[0];
    const float* c1w = (const float*)d_in[1];
    const float* c1b = (const float*)d_in[2];
    const float* pw  = (const float*)d_in[3];
    const float* pb  = (const float*)d_in[4];
    const float* rw  = (const float*)d_in[5];
    const float* w1  = (const float*)d_in[6];
    const float* b1  = (const float*)d_in[7];
    const float* w2  = (const float*)d_in[8];
    const float* b2  = (const float*)d_in[9];
    const float* w3  = (const float*)d_in[10];
    const float* b3  = (const float*)d_in[11];
    float* out = (float*)d_out;
    float* out_classes = out;              // [512,10]
    float* out_recon   = out + 512 * NC;   // [512,784]

    void *p_d1, *p_d2;
    cudaGetSymbolAddress(&p_d1, g_d1);
    cudaGetSymbolAddress(&p_d2, g_d2);

    prep_w_kernel<<<256, 256>>>(pw);                    // launch 1
    prep_rw_kernel<<<dim3(36, 4, 10), 256>>>(rw);       // launch 2
    conv1_kernel<<<dim3(8, 256), 640>>>(x, c1w, c1b);   // launch 3

    int c2sm = 2 * C2_BUFSZ;  // 218112 B
    cudaFuncSetAttribute(conv2_mma_kernel, cudaFuncAttributeMaxDynamicSharedMemorySize, c2sm);
    conv2_mma_kernel<<<128, 512, c2sm>>>(pb);           // launch 4 (profiled slot)

    routing_kernel<<<dim3(10, 512), 288>>>();

    classes_kernel<<<512, 32>>>(out_classes);

    gemm1s_kernel<<<1024, 256>>>(w1, b1, (float*)p_d1);
    gemm_kernel<<<dim3(16, 8), 256>>>((const float*)p_d1, w2, b2, (float*)p_d2, 1024, 512, 0);
    gemm_kernel<<<dim3(13, 8), 256>>>((const float*)p_d2, w3, b3, out_recon, 784, 1024, 1);
}

// round 15
// speedup vs baseline: 1.5677x; 1.5677x over previous
#include <cuda_runtime.h>
#include <cuda_bf16.h>
#include <math.h>
#include <stdint.h>

#define NC 10

// ---------------- scratch (static device arrays; no runtime allocation) ----------------
__device__ __nv_bfloat16 g_hh[52428800];  // [512 b][20 y][20 x][256 c] conv1 out, bf16 hi
__device__ __nv_bfloat16 g_hl[52428800];  // same, bf16 lo (residual)
__device__ __nv_bfloat16 g_wh[5308416];   // [81 dydx][256 ci][256 oc] weights hi
__device__ __nv_bfloat16 g_wl[5308416];   // weights lo
__device__ float g_rw2[1474560];          // [10 c][128 io][1152 r] transposed route_w
__device__ float g_u[4718592];            // [512][1152][8] primary capsules (squashed)
__device__ float g_caps[81920];           // [512][10][16]
__device__ int   g_am[512];               // argmax class per image
__device__ float g_c16[8192];             // [512][16] winning capsule
__device__ float g_d1[262144];            // [512][512]
__device__ float g_d2[524288];            // [512][1024]

// ---------------- PTX helpers (all baseline sm_80+; no arch-'a' features) ----------------
__device__ __forceinline__ void ffma2(float2& c, const float2 a, const float2 b) {
    asm("fma.rn.f32x2 %0, %1, %2, %0;"
        : "+l"(reinterpret_cast<unsigned long long&>(c))
        : "l"(reinterpret_cast<const unsigned long long&>(a)),
          "l"(reinterpret_cast<const unsigned long long&>(b)));
}
__device__ __forceinline__ void cp16(uint32_t d, const void* s) {
    asm volatile("cp.async.cg.shared.global [%0], [%1], 16;" :: "r"(d), "l"(s));
}
__device__ __forceinline__ void cp_commit() { asm volatile("cp.async.commit_group;"); }
__device__ __forceinline__ void cp_wait0()  { asm volatile("cp.async.wait_group 0;" ::: "memory"); }

__device__ __forceinline__ void ldsm4(uint32_t* r, uint32_t addr) {
    asm volatile("ldmatrix.sync.aligned.m8n8.x4.shared.b16 {%0,%1,%2,%3}, [%4];"
        : "=r"(r[0]), "=r"(r[1]), "=r"(r[2]), "=r"(r[3]) : "r"(addr));
}
__device__ __forceinline__ void ldsm4t(uint32_t* r, uint32_t addr) {
    asm volatile("ldmatrix.sync.aligned.m8n8.x4.trans.shared.b16 {%0,%1,%2,%3}, [%4];"
        : "=r"(r[0]), "=r"(r[1]), "=r"(r[2]), "=r"(r[3]) : "r"(addr));
}
__device__ __forceinline__ void mma16816(float* c, const uint32_t* a, const uint32_t* b) {
    asm volatile("mma.sync.aligned.m16n8k16.row.col.f32.bf16.bf16.f32 "
        "{%0,%1,%2,%3}, {%4,%5,%6,%7}, {%8,%9}, {%0,%1,%2,%3};"
        : "+f"(c[0]), "+f"(c[1]), "+f"(c[2]), "+f"(c[3])
        : "r"(a[0]), "r"(a[1]), "r"(a[2]), "r"(a[3]), "r"(b[0]), "r"(b[1]));
}

// ---------------- weight prep: prim_w -> [dydx][ci][oc] hi/lo bf16 ----------------
__global__ __launch_bounds__(256) void prep_w_kernel(const float* __restrict__ pw) {
    int idx = blockIdx.x * 256 + threadIdx.x;   // 65536 = ci*256 + oc
    int ci = idx >> 8, oc = idx & 255;
    const float* src = pw + (size_t)(oc * 256 + ci) * 81;
#pragma unroll 3
    for (int k = 0; k < 81; k++) {
        float w = src[k];
        __nv_bfloat16 hi = __float2bfloat16(w);
        __nv_bfloat16 lo = __float2bfloat16(w - __bfloat162float(hi));
        size_t o = ((size_t)k * 256 + ci) * 256 + oc;
        g_wh[o] = hi;
        g_wl[o] = lo;
    }
}

// ---------------- route_w transpose: [c][r][i][o] -> [c][io][r] ----------------
__global__ __launch_bounds__(256) void prep_rw_kernel(const float* __restrict__ rw) {
    __shared__ float tile[32][33];
    int rb = blockIdx.x, iob = blockIdx.y, c = blockIdx.z;
    int tx = threadIdx.x & 31, ty = threadIdx.x >> 5;   // ty 0..7
#pragma unroll
    for (int k = 0; k < 4; k++) {
        int r = rb * 32 + ty * 4 + k;
        tile[ty * 4 + k][tx] = rw[((size_t)c * 1152 + r) * 128 + iob * 32 + tx];
    }
    __syncthreads();
#pragma unroll
    for (int k = 0; k < 4; k++) {
        int io = iob * 32 + ty * 4 + k;
        g_rw2[((size_t)c * 128 + io) * 1152 + rb * 32 + tx] = tile[tx][ty * 4 + k];
    }
}

// ---------------- conv1: 2 images/block via FFMA2 -> relu -> NHWC bf16 hi/lo ----------------
__global__ __launch_bounds__(640) void conv1_kernel(const float* __restrict__ x,
                                                    const float* __restrict__ w,
                                                    const float* __restrict__ bias) {
    __shared__ __align__(16) float2 img2[784];
    __shared__ float ws[2592];
    __shared__ float bs[32];
    int bp = blockIdx.y, ocg = blockIdx.x, t = threadIdx.x;
    const float* x0 = x + (size_t)(bp * 2) * 784;
    const float* x1 = x0 + 784;
    for (int i = t; i < 784; i += 640) img2[i] = make_float2(x0[i], x1[i]);
    for (int i = t; i < 2592; i += 640) ws[i] = w[(size_t)ocg * 2592 + i];
    if (t < 32) bs[t] = bias[ocg * 32 + t];
    __syncthreads();
    int oc = t & 31, y = t >> 5;
    float2 acc[20];
#pragma unroll
    for (int i = 0; i < 20; i++) acc[i] = make_float2(0.f, 0.f);
    for (int dy = 0; dy < 9; dy++) {
        const float2* rp = img2 + (y + dy) * 28;
        const float* wrow = ws + oc * 81 + dy * 9;
#pragma unroll
        for (int q = 0; q < 4; q++) {          // xo quarters of 5, cols q*5 .. q*5+12
            float2 r[14];
#pragma unroll
            for (int i = 0; i < 14; i++) r[i] = rp[q * 5 + i];
#pragma unroll
            for (int dx = 0; dx < 9; dx++) {
                float wv = wrow[dx];
                float2 w2 = make_float2(wv, wv);
#pragma unroll
                for (int xo = 0; xo < 5; xo++)
                    ffma2(acc[q * 5 + xo], w2, r[xo + dx]);
            }
        }
    }
    float bv = bs[oc];
    size_t base0 = (((size_t)(bp * 2) * 20 + y) * 20) * 256 + ocg * 32 + oc;
    size_t base1 = base0 + (size_t)400 * 256;
#pragma unroll
    for (int i = 0; i < 20; i++) {
        float v0 = fmaxf(acc[i].x + bv, 0.f);
        float v1 = fmaxf(acc[i].y + bv, 0.f);
        __nv_bfloat16 h0 = __float2bfloat16(v0);
        __nv_bfloat16 h1 = __float2bfloat16(v1);
        g_hh[base0 + (size_t)i * 256] = h0;
        g_hl[base0 + (size_t)i * 256] = __float2bfloat16(v0 - __bfloat162float(h0));
        g_hh[base1 + (size_t)i * 256] = h1;
        g_hl[base1 + (size_t)i * 256] = __float2bfloat16(v1 - __bfloat162float(h1));
    }
}

// ---------------- conv2 via mma.sync bf16 (hi/lo, 3 passes) + fused bias/squash ----------------
// R7 tiling (proven ceiling for this path): 512 thr / 16 warps, warp w owns N=16, 9 m-tiles.
// Single __syncthreads per step: [wait0; sync; stage s+1; compute s].
#define C2_AHI   0u
#define C2_ALO   20736u
#define C2_BHI   41472u
#define C2_BLO   75264u
#define C2_BUFSZ 109056u
#define C2_STEPS 324

__global__ __launch_bounds__(512, 1) void conv2_mma_kernel(const float* __restrict__ bias) {
    extern __shared__ __align__(16) char smc[];
    uint32_t smb = (uint32_t)__cvta_generic_to_shared(smc);
    int t = threadIdx.x;
    int bq = blockIdx.x;
    int w = t >> 5, T = t & 31;

    // A staging descriptors
    uint32_t asrc[3], adst[3]; int an = 0;
#pragma unroll
    for (int i = 0; i < 3; i++) {
        int idx = t + i * 512;
        if (idx < 1152) {
            int row = idx >> 3, c = idx & 7;
            int img = row / 36, p = row - img * 36, oy = p / 6, ox = p - oy * 6;
            asrc[an] = (uint32_t)((((long)(bq * 4 + img) * 400 + (long)(2 * oy) * 20 + 2 * ox) * 256 + c * 8) * 2);
            adst[an] = (uint32_t)(row * 144 + c * 16);
            an++;
        }
    }
    // B staging: affine in i (idx += 512 -> row += 16)
    uint32_t bsrc0, bdst0;
    {
        int row = t >> 5, c = t & 31;
        bsrc0 = (uint32_t)((row * 256 + c * 8) * 2);   // += 8192 per i
        bdst0 = (uint32_t)(row * 528 + c * 16);        // += 8448 per i
    }
    const char* hh = (const char*)g_hh;
    const char* hl = (const char*)g_hl;
    const char* wh = (const char*)g_wh;
    const char* wl = (const char*)g_wl;

    // prologue: stage step 0 into buffer 0
    {
        uint32_t ba = smb;
        for (int i = 0; i < an; i++) {
            cp16(ba + C2_AHI + adst[i], hh + asrc[i]);
            cp16(ba + C2_ALO + adst[i], hl + asrc[i]);
        }
#pragma unroll
        for (int i = 0; i < 4; i++) {
            cp16(ba + C2_BHI + bdst0 + i * 8448u, wh + bsrc0 + i * 8192u);
            cp16(ba + C2_BLO + bdst0 + i * 8448u, wl + bsrc0 + i * 8192u);
        }
        cp_commit();
    }

    float acc[9][2][4];
#pragma unroll
    for (int m = 0; m < 9; m++)
#pragma unroll
        for (int n = 0; n < 2; n++)
#pragma unroll
            for (int i = 0; i < 4; i++) acc[m][n][i] = 0.f;

    uint32_t arow = (uint32_t)((T & 15) * 144 + ((T & 16) ? 16 : 0));
    uint32_t brow = (uint32_t)((T & 15) * 528 + w * 32 + ((T & 16) ? 16 : 0));

    for (int s = 0; s < C2_STEPS; s++) {
        cp_wait0();          // step-s data arrived
        __syncthreads();     // all warps done reading buf[(s+1)&1] (step s-1)
        if (s + 1 < C2_STEPS) {
            int s1 = s + 1, dydx = s1 >> 2, ci0 = (s1 & 3) * 64;
            int dy = dydx / 9, dx = dydx - dy * 9;
            uint32_t stepA = (uint32_t)(((dy * 20 + dx) * 256 + ci0) * 2);
            uint32_t stepB = (uint32_t)(((dydx * 256 + ci0) * 256) * 2);
            uint32_t ba = smb + (uint32_t)((s1 & 1) ? C2_BUFSZ : 0u);
            for (int i = 0; i < an; i++) {
                cp16(ba + C2_AHI + adst[i], hh + asrc[i] + stepA);
                cp16(ba + C2_ALO + adst[i], hl + asrc[i] + stepA);
            }
#pragma unroll
            for (int i = 0; i < 4; i++) {
                cp16(ba + C2_BHI + bdst0 + i * 8448u, wh + bsrc0 + stepB + i * 8192u);
                cp16(ba + C2_BLO + bdst0 + i * 8448u, wl + bsrc0 + stepB + i * 8192u);
            }
            cp_commit();
        }
        uint32_t base = smb + (uint32_t)((s & 1) ? C2_BUFSZ : 0u);
        uint32_t Ah = base + C2_AHI, Al = base + C2_ALO;
        uint32_t Bh = base + C2_BHI, Bl = base + C2_BLO;
#pragma unroll
        for (int kk = 0; kk < 4; kk++) {
            uint32_t bh[4], bl[4];
            uint32_t bo = (uint32_t)(kk * 16 * 528) + brow;
            ldsm4t(bh, Bh + bo);
            ldsm4t(bl, Bl + bo);
#pragma unroll
            for (int mt = 0; mt < 9; mt++) {
                uint32_t ah[4], al[4];
                uint32_t ao = (uint32_t)(mt * 16 * 144 + kk * 32) + arow;
                ldsm4(ah, Ah + ao);
                ldsm4(al, Al + ao);
                mma16816(acc[mt][0], ah, bh);
                mma16816(acc[mt][1], ah, bh + 2);
                mma16816(acc[mt][0], ah, bl);
                mma16816(acc[mt][1], ah, bl + 2);
                mma16816(acc[mt][0], al, bh);
                mma16816(acc[mt][1], al, bh + 2);
            }
        }
    }

    // ---- fused epilogue: bias add -> smem [img][p][m][9] -> squash -> g_u ----
    __syncthreads();                       // everyone done with step 323's buffer
    float* S = (float*)smc;                // 4*36*32*9 floats = 165888 B
    int gid = T >> 2, tig = T & 3;
#pragma unroll
    for (int nt = 0; nt < 2; nt++) {
        int oc0 = w * 16 + nt * 8 + tig * 2;
        int oc1 = oc0 + 1;
        float bv0 = bias[oc0], bv1 = bias[oc1];
        int off0 = (oc0 & 31) * 9 + (oc0 >> 5);
        int off1 = (oc1 & 31) * 9 + (oc1 >> 5);
#pragma unroll
        for (int mt = 0; mt < 9; mt++) {
#pragma unroll
            for (int h = 0; h < 2; h++) {
                int row = mt * 16 + gid + h * 8;
                int img = row / 36, p = row - img * 36;
                int base = (img * 36 + p) * 288;   // 32*9
                S[base + off0] = acc[mt][nt][h * 2 + 0] + bv0;
                S[base + off1] = acc[mt][nt][h * 2 + 1] + bv1;
            }
        }
    }
    __syncthreads();
#pragma unroll
    for (int k = 0; k < 9; k++) {
        int c = t + k * 512;                // 4608 capsules: c = img*1152 + r, r = m*36+p
        int img = c / 1152;
        int r = c - img * 1152;
        int m = r / 36, p = r - m * 36;
        const float* sp = S + (img * 36 + p) * 288 + m * 9;
        float v0 = sp[0], v1 = sp[1], v2 = sp[2], v3 = sp[3];
        float v4 = sp[4], v5 = sp[5], v6 = sp[6], v7 = sp[7];
        float sq = v0*v0 + v1*v1 + v2*v2 + v3*v3 + v4*v4 + v5*v5 + v6*v6 + v7*v7;
        float sc = sq / ((1.f + sq) * sqrtf(sq));
        float4* dst = (float4*)(g_u + ((size_t)(bq * 4 + img) * 1152 + r) * 8);
        dst[0] = make_float4(v0 * sc, v1 * sc, v2 * sc, v3 * sc);
        dst[1] = make_float4(v4 * sc, v5 * sc, v6 * sc, v7 * sc);
    }
}

// ---------------- routing: block = (class, image), 288 threads x 4 consecutive routes ----------
// route_w loads are float4 (transposed layout), u loads are float4. 2 CTAs/SM. (R11 config)
__global__ __launch_bounds__(288, 2) void routing_kernel() {
    __shared__ float red[9][17];
    __shared__ float mred[9];
    int c = blockIdx.x, b = blockIdx.y, t = threadIdx.x;
    int lane = t & 31, wid = t >> 5;
    const float4* w4 = (const float4*)(g_rw2 + (size_t)c * 147456);
    const float4* up = (const float4*)(g_u + (size_t)b * 9216 + (size_t)t * 32);

    // u values for 4 consecutive routes (4t .. 4t+3)
    float uu[4][8];
#pragma unroll
    for (int j = 0; j < 4; j++) {
        float4 a = up[j * 2], bb = up[j * 2 + 1];
        uu[j][0] = a.x; uu[j][1] = a.y; uu[j][2] = a.z; uu[j][3] = a.w;
        uu[j][4] = bb.x; uu[j][5] = bb.y; uu[j][6] = bb.z; uu[j][7] = bb.w;
    }

    float pr[4][16];
#pragma unroll
    for (int j = 0; j < 4; j++)
#pragma unroll
        for (int o = 0; o < 16; o++) pr[j][o] = 0.f;

#pragma unroll
    for (int i = 0; i < 8; i++) {
#pragma unroll
        for (int o = 0; o < 16; o++) {
            float4 wv = w4[(size_t)(i * 16 + o) * 288 + t];
            pr[0][o] = fmaf(uu[0][i], wv.x, pr[0][o]);
            pr[1][o] = fmaf(uu[1][i], wv.y, pr[1][o]);
            pr[2][o] = fmaf(uu[2][i], wv.z, pr[2][o]);
            pr[3][o] = fmaf(uu[3][i], wv.w, pr[3][o]);
        }
    }

    float lg[4] = {0.f, 0.f, 0.f, 0.f};
    float s[16];
    for (int it = 0; it < 3; it++) {
        // block max of logits
        float mx = fmaxf(fmaxf(lg[0], lg[1]), fmaxf(lg[2], lg[3]));
#pragma unroll
        for (int off = 16; off; off >>= 1) mx = fmaxf(mx, __shfl_xor_sync(0xffffffffu, mx, off));
        if (lane == 0) mred[wid] = mx;
        __syncthreads();
        float M = mred[0];
#pragma unroll
        for (int ww = 1; ww < 9; ww++) M = fmaxf(M, mred[ww]);

        // weighted sums
#pragma unroll
        for (int o = 0; o < 16; o++) s[o] = 0.f;
        float z = 0.f;
#pragma unroll
        for (int j = 0; j < 4; j++) {
            float e = expf(lg[j] - M);
            z += e;
#pragma unroll
            for (int o = 0; o < 16; o++) s[o] = fmaf(e, pr[j][o], s[o]);
        }
#pragma unroll
        for (int off = 16; off; off >>= 1) {
            z += __shfl_xor_sync(0xffffffffu, z, off);
#pragma unroll
            for (int o = 0; o < 16; o++) s[o] += __shfl_xor_sync(0xffffffffu, s[o], off);
        }
        if (lane == 0) {
#pragma unroll
            for (int o = 0; o < 16; o++) red[wid][o] = s[o];
            red[wid][16] = z;
        }
        __syncthreads();
        float Z = 0.f;
#pragma unroll
        for (int o = 0; o < 16; o++) s[o] = 0.f;
#pragma unroll
        for (int ww = 0; ww < 9; ww++) {
            Z += red[ww][16];
#pragma unroll
            for (int o = 0; o < 16; o++) s[o] += red[ww][o];
        }
        float q = 0.f;
#pragma unroll
        for (int o = 0; o < 16; o++) { s[o] /= Z; q = fmaf(s[o], s[o], q); }
        float sc = q / ((1.f + q) * sqrtf(q));
#pragma unroll
        for (int o = 0; o < 16; o++) s[o] *= sc;
        if (it < 2) {
#pragma unroll
            for (int j = 0; j < 4; j++) {
                float d = 0.f;
#pragma unroll
                for (int o = 0; o < 16; o++) d = fmaf(pr[j][o], s[o], d);
                lg[j] += d;
            }
        }
        __syncthreads();   // protect red/mred before next iteration's writes
    }
    if (t == 0) {
        float* cp = g_caps + ((size_t)b * NC + c) * 16;
#pragma unroll
        for (int o = 0; o < 16; o++) cp[o] = s[o];
    }
}

// ---------------- classes softmax + argmax -> compact decoder input ----------------
__global__ void classes_kernel(float* __restrict__ out_classes) {
    int b = blockIdx.x, lane = threadIdx.x;  // 32 threads
    float n2 = 0.f;
    if (lane < NC) {
        const float* cp = g_caps + ((size_t)b * NC + lane) * 16;
#pragma unroll
        for (int o = 0; o < 16; o++) n2 = fmaf(cp[o], cp[o], n2);
    }
    float nrm = (lane < NC) ? sqrtf(n2) : -3.0e38f;
    float mx = nrm;
#pragma unroll
    for (int off = 16; off; off >>= 1) mx = fmaxf(mx, __shfl_xor_sync(0xffffffffu, mx, off));
    float e = (lane < NC) ? expf(nrm - mx) : 0.f;
    float zz = e;
#pragma unroll
    for (int off = 16; off; off >>= 1) zz += __shfl_xor_sync(0xffffffffu, zz, off);
    if (lane < NC) out_classes[b * NC + lane] = e / zz;
    unsigned msk = __ballot_sync(0xffffffffu, nrm == mx);
    int am = __ffs(msk) - 1;   // first (lowest-index) max, matches jnp.argmax
    const float* ap = g_caps + ((size_t)b * NC + am) * 16;
    if (lane < 16) g_c16[b * 16 + lane] = ap[lane];
    if (lane == 0) g_am[b] = am;
}

// ---------------- sparse decoder layer 1: d1 = relu(W1[:, am*16 : am*16+16] @ c16 + b1) ------
__global__ __launch_bounds__(256) void gemm1s_kernel(const float* __restrict__ W1,
                                                     const float* __restrict__ b1v,
                                                     float* __restrict__ d1) {
    int idx = blockIdx.x * 256 + threadIdx.x;   // 512*512 outputs
    int row = idx >> 9, n = idx & 511;
    int am = g_am[row];
    const float4* wp = (const float4*)(W1 + (size_t)n * 160 + am * 16);
    const float4* cp = (const float4*)(g_c16 + row * 16);
    float acc = 0.f;
#pragma unroll
    for (int q = 0; q < 4; q++) {
        float4 wv = wp[q], cv = cp[q];
        acc = fmaf(wv.x, cv.x, acc);
        acc = fmaf(wv.y, cv.y, acc);
        acc = fmaf(wv.z, cv.z, acc);
        acc = fmaf(wv.w, cv.w, acc);
    }
    d1[idx] = fmaxf(acc + b1v[n], 0.f);
}

// ---------------- decoder GEMM: C[512,N] = act(A[512,K] @ W[N,K]^T + bias) ----------------
__global__ __launch_bounds__(256) void gemm_kernel(const float* __restrict__ A,
                                                   const float* __restrict__ W,
                                                   const float* __restrict__ bias,
                                                   float* __restrict__ C,
                                                   int N, int K, int act) {
    __shared__ float As[64][33];
    __shared__ float Bs[64][33];
    int tx = threadIdx.x & 15, ty = threadIdx.x >> 4;
    int m0 = blockIdx.y * 64, n0 = blockIdx.x * 64;
    float acc[4][4];
#pragma unroll
    for (int i = 0; i < 4; i++)
#pragma unroll
        for (int j = 0; j < 4; j++) acc[i][j] = 0.f;
    for (int k0 = 0; k0 < K; k0 += 32) {
        __syncthreads();
        for (int idx = threadIdx.x; idx < 2048; idx += 256) {
            int mm = idx >> 5, kk = idx & 31;
            As[mm][kk] = A[(size_t)(m0 + mm) * K + k0 + kk];
            Bs[mm][kk] = (n0 + mm < N) ? W[(size_t)(n0 + mm) * K + k0 + kk] : 0.f;
        }
        __syncthreads();
#pragma unroll
        for (int kk = 0; kk < 32; kk++) {
            float a[4], bb[4];
#pragma unroll
            for (int i = 0; i < 4; i++) a[i] = As[ty * 4 + i][kk];
#pragma unroll
            for (int j = 0; j < 4; j++) bb[j] = Bs[tx * 4 + j][kk];
#pragma unroll
            for (int i = 0; i < 4; i++)
#pragma unroll
                for (int j = 0; j < 4; j++) acc[i][j] = fmaf(a[i], bb[j], acc[i][j]);
        }
    }
#pragma unroll
    for (int i = 0; i < 4; i++) {
        int cm = m0 + ty * 4 + i;
#pragma unroll
        for (int j = 0; j < 4; j++) {
            int cn = n0 + tx * 4 + j;
            if (cn < N) {
                float val = acc[i][j] + bias[cn];
                val = act ? (1.f / (1.f + expf(-val))) : fmaxf(val, 0.f);
                C[(size_t)cm * N + cn] = val;
            }
        }
    }
}

extern "C" void kernel_launch(void* const* d_in, const int* in_sizes, int n_in,
                              void* d_out, int out_size) {
    const float* x   = (const float*)d_in[0];
    const float* c1w = (const float*)d_in[1];
    const float* c1b = (const float*)d_in[2];
    const float* pw  = (const float*)d_in[3];
    const float* pb  = (const float*)d_in[4];
    const float* rw  = (const float*)d_in[5];
    const float* w1  = (const float*)d_in[6];
    const float* b1  = (const float*)d_in[7];
    const float* w2  = (const float*)d_in[8];
    const float* b2  = (const float*)d_in[9];
    const float* w3  = (const float*)d_in[10];
    const float* b3  = (const float*)d_in[11];
    float* out = (float*)d_out;
    float* out_classes = out;              // [512,10]
    float* out_recon   = out + 512 * NC;   // [512,784]

    void *p_d1, *p_d2;
    cudaGetSymbolAddress(&p_d1, g_d1);
    cudaGetSymbolAddress(&p_d2, g_d2);

    prep_w_kernel<<<256, 256>>>(pw);                    // launch 1
    prep_rw_kernel<<<dim3(36, 4, 10), 256>>>(rw);       // launch 2
    conv1_kernel<<<dim3(8, 256), 640>>>(x, c1w, c1b);   // launch 3

    int c2sm = 2 * C2_BUFSZ;  // 218112 B
    cudaFuncSetAttribute(conv2_mma_kernel, cudaFuncAttributeMaxDynamicSharedMemorySize, c2sm);
    conv2_mma_kernel<<<128, 512, c2sm>>>(pb);           // launch 4 (profiled slot)

    routing_kernel<<<dim3(10, 512), 288>>>();

    classes_kernel<<<512, 32>>>(out_classes);

    gemm1s_kernel<<<1024, 256>>>(w1, b1, (float*)p_d1);
    gemm_kernel<<<dim3(16, 8), 256>>>((const float*)p_d1, w2, b2, (float*)p_d2, 1024, 512, 0);
    gemm_kernel<<<dim3(13, 8), 256>>>((const float*)p_d2, w3, b3, out_recon, 784, 1024, 1);
}

// round 16
// speedup vs baseline: 1.5682x; 1.0003x over previous
#include <cuda_runtime.h>
#include <cuda_bf16.h>
#include <math.h>
#include <stdint.h>

#define NC 10

// ---------------- scratch (static device arrays; no runtime allocation) ----------------
__device__ __nv_bfloat16 g_hh[52428800];  // [512 b][20 y][20 x][256 c] conv1 out, bf16 hi
__device__ __nv_bfloat16 g_hl[52428800];  // same, bf16 lo (residual)
__device__ __nv_bfloat16 g_wh[5308416];   // [81 dydx][256 ci][256 oc] weights hi
__device__ __nv_bfloat16 g_wl[5308416];   // weights lo
__device__ float g_rw2[1474560];          // [10 c][128 io][1152 r] transposed route_w
__device__ float g_u[4718592];            // [512][1152][8] primary capsules (squashed)
__device__ float g_caps[81920];           // [512][10][16]
__device__ int   g_am[512];               // argmax class per image
__device__ float g_c16[8192];             // [512][16] winning capsule
__device__ float g_d1[262144];            // [512][512]
__device__ float g_d2[524288];            // [512][1024]

// ---------------- PTX helpers (all baseline sm_80+; no arch-'a' features) ----------------
__device__ __forceinline__ void ffma2(float2& c, const float2 a, const float2 b) {
    asm("fma.rn.f32x2 %0, %1, %2, %0;"
        : "+l"(reinterpret_cast<unsigned long long&>(c))
        : "l"(reinterpret_cast<const unsigned long long&>(a)),
          "l"(reinterpret_cast<const unsigned long long&>(b)));
}
__device__ __forceinline__ void cp16(uint32_t d, const void* s) {
    asm volatile("cp.async.cg.shared.global [%0], [%1], 16;" :: "r"(d), "l"(s));
}
__device__ __forceinline__ void cp_commit() { asm volatile("cp.async.commit_group;"); }
__device__ __forceinline__ void cp_wait0()  { asm volatile("cp.async.wait_group 0;" ::: "memory"); }

__device__ __forceinline__ void ldsm4(uint32_t* r, uint32_t addr) {
    asm volatile("ldmatrix.sync.aligned.m8n8.x4.shared.b16 {%0,%1,%2,%3}, [%4];"
        : "=r"(r[0]), "=r"(r[1]), "=r"(r[2]), "=r"(r[3]) : "r"(addr));
}
__device__ __forceinline__ void ldsm4t(uint32_t* r, uint32_t addr) {
    asm volatile("ldmatrix.sync.aligned.m8n8.x4.trans.shared.b16 {%0,%1,%2,%3}, [%4];"
        : "=r"(r[0]), "=r"(r[1]), "=r"(r[2]), "=r"(r[3]) : "r"(addr));
}
__device__ __forceinline__ void mma16816(float* c, const uint32_t* a, const uint32_t* b) {
    asm volatile("mma.sync.aligned.m16n8k16.row.col.f32.bf16.bf16.f32 "
        "{%0,%1,%2,%3}, {%4,%5,%6,%7}, {%8,%9}, {%0,%1,%2,%3};"
        : "+f"(c[0]), "+f"(c[1]), "+f"(c[2]), "+f"(c[3])
        : "r"(a[0]), "r"(a[1]), "r"(a[2]), "r"(a[3]), "r"(b[0]), "r"(b[1]));
}

// ---------------- weight prep: prim_w -> [dydx][ci][oc] hi/lo bf16 ----------------
__global__ __launch_bounds__(256) void prep_w_kernel(const float* __restrict__ pw) {
    int idx = blockIdx.x * 256 + threadIdx.x;   // 65536 = ci*256 + oc
    int ci = idx >> 8, oc = idx & 255;
    const float* src = pw + (size_t)(oc * 256 + ci) * 81;
#pragma unroll 3
    for (int k = 0; k < 81; k++) {
        float w = src[k];
        __nv_bfloat16 hi = __float2bfloat16(w);
        __nv_bfloat16 lo = __float2bfloat16(w - __bfloat162float(hi));
        size_t o = ((size_t)k * 256 + ci) * 256 + oc;
        g_wh[o] = hi;
        g_wl[o] = lo;
    }
}

// ---------------- route_w transpose: [c][r][i][o] -> [c][io][r] ----------------
__global__ __launch_bounds__(256) void prep_rw_kernel(const float* __restrict__ rw) {
    __shared__ float tile[32][33];
    int rb = blockIdx.x, iob = blockIdx.y, c = blockIdx.z;
    int tx = threadIdx.x & 31, ty = threadIdx.x >> 5;   // ty 0..7
#pragma unroll
    for (int k = 0; k < 4; k++) {
        int r = rb * 32 + ty * 4 + k;
        tile[ty * 4 + k][tx] = rw[((size_t)c * 1152 + r) * 128 + iob * 32 + tx];
    }
    __syncthreads();
#pragma unroll
    for (int k = 0; k < 4; k++) {
        int io = iob * 32 + ty * 4 + k;
        g_rw2[((size_t)c * 128 + io) * 1152 + rb * 32 + tx] = tile[tx][ty * 4 + k];
    }
}

// ---------------- conv1: 2 images/block via FFMA2 -> relu -> NHWC bf16 hi/lo ----------------
__global__ __launch_bounds__(640) void conv1_kernel(const float* __restrict__ x,
                                                    const float* __restrict__ w,
                                                    const float* __restrict__ bias) {
    __shared__ __align__(16) float2 img2[784];
    __shared__ float ws[2592];
    __shared__ float bs[32];
    int bp = blockIdx.y, ocg = blockIdx.x, t = threadIdx.x;
    const float* x0 = x + (size_t)(bp * 2) * 784;
    const float* x1 = x0 + 784;
    for (int i = t; i < 784; i += 640) img2[i] = make_float2(x0[i], x1[i]);
    for (int i = t; i < 2592; i += 640) ws[i] = w[(size_t)ocg * 2592 + i];
    if (t < 32) bs[t] = bias[ocg * 32 + t];
    __syncthreads();
    int oc = t & 31, y = t >> 5;
    float2 acc[20];
#pragma unroll
    for (int i = 0; i < 20; i++) acc[i] = make_float2(0.f, 0.f);
    for (int dy = 0; dy < 9; dy++) {
        const float2* rp = img2 + (y + dy) * 28;
        const float* wrow = ws + oc * 81 + dy * 9;
#pragma unroll
        for (int q = 0; q < 4; q++) {          // xo quarters of 5, cols q*5 .. q*5+12
            float2 r[14];
#pragma unroll
            for (int i = 0; i < 14; i++) r[i] = rp[q * 5 + i];
#pragma unroll
            for (int dx = 0; dx < 9; dx++) {
                float wv = wrow[dx];
                float2 w2 = make_float2(wv, wv);
#pragma unroll
                for (int xo = 0; xo < 5; xo++)
                    ffma2(acc[q * 5 + xo], w2, r[xo + dx]);
            }
        }
    }
    float bv = bs[oc];
    size_t base0 = (((size_t)(bp * 2) * 20 + y) * 20) * 256 + ocg * 32 + oc;
    size_t base1 = base0 + (size_t)400 * 256;
#pragma unroll
    for (int i = 0; i < 20; i++) {
        float v0 = fmaxf(acc[i].x + bv, 0.f);
        float v1 = fmaxf(acc[i].y + bv, 0.f);
        __nv_bfloat16 h0 = __float2bfloat16(v0);
        __nv_bfloat16 h1 = __float2bfloat16(v1);
        g_hh[base0 + (size_t)i * 256] = h0;
        g_hl[base0 + (size_t)i * 256] = __float2bfloat16(v0 - __bfloat162float(h0));
        g_hh[base1 + (size_t)i * 256] = h1;
        g_hl[base1 + (size_t)i * 256] = __float2bfloat16(v1 - __bfloat162float(h1));
    }
}

// ---------------- conv2 via mma.sync bf16 (hi/lo, 3 passes) + fused bias/squash ----------------
// R7 tiling (proven ceiling for this path): 512 thr / 16 warps, warp w owns N=16, 9 m-tiles.
// Single __syncthreads per step: [wait0; sync; stage s+1; compute s].
#define C2_AHI   0u
#define C2_ALO   20736u
#define C2_BHI   41472u
#define C2_BLO   75264u
#define C2_BUFSZ 109056u
#define C2_STEPS 324

__global__ __launch_bounds__(512, 1) void conv2_mma_kernel(const float* __restrict__ bias) {
    extern __shared__ __align__(16) char smc[];
    uint32_t smb = (uint32_t)__cvta_generic_to_shared(smc);
    int t = threadIdx.x;
    int bq = blockIdx.x;
    int w = t >> 5, T = t & 31;

    // A staging descriptors
    uint32_t asrc[3], adst[3]; int an = 0;
#pragma unroll
    for (int i = 0; i < 3; i++) {
        int idx = t + i * 512;
        if (idx < 1152) {
            int row = idx >> 3, c = idx & 7;
            int img = row / 36, p = row - img * 36, oy = p / 6, ox = p - oy * 6;
            asrc[an] = (uint32_t)((((long)(bq * 4 + img) * 400 + (long)(2 * oy) * 20 + 2 * ox) * 256 + c * 8) * 2);
            adst[an] = (uint32_t)(row * 144 + c * 16);
            an++;
        }
    }
    // B staging: affine in i (idx += 512 -> row += 16)
    uint32_t bsrc0, bdst0;
    {
        int row = t >> 5, c = t & 31;
        bsrc0 = (uint32_t)((row * 256 + c * 8) * 2);   // += 8192 per i
        bdst0 = (uint32_t)(row * 528 + c * 16);        // += 8448 per i
    }
    const char* hh = (const char*)g_hh;
    const char* hl = (const char*)g_hl;
    const char* wh = (const char*)g_wh;
    const char* wl = (const char*)g_wl;

    // prologue: stage step 0 into buffer 0
    {
        uint32_t ba = smb;
        for (int i = 0; i < an; i++) {
            cp16(ba + C2_AHI + adst[i], hh + asrc[i]);
            cp16(ba + C2_ALO + adst[i], hl + asrc[i]);
        }
#pragma unroll
        for (int i = 0; i < 4; i++) {
            cp16(ba + C2_BHI + bdst0 + i * 8448u, wh + bsrc0 + i * 8192u);
            cp16(ba + C2_BLO + bdst0 + i * 8448u, wl + bsrc0 + i * 8192u);
        }
        cp_commit();
    }

    float acc[9][2][4];
#pragma unroll
    for (int m = 0; m < 9; m++)
#pragma unroll
        for (int n = 0; n < 2; n++)
#pragma unroll
            for (int i = 0; i < 4; i++) acc[m][n][i] = 0.f;

    uint32_t arow = (uint32_t)((T & 15) * 144 + ((T & 16) ? 16 : 0));
    uint32_t brow = (uint32_t)((T & 15) * 528 + w * 32 + ((T & 16) ? 16 : 0));

    for (int s = 0; s < C2_STEPS; s++) {
        cp_wait0();          // step-s data arrived
        __syncthreads();     // all warps done reading buf[(s+1)&1] (step s-1)
        if (s + 1 < C2_STEPS) {
            int s1 = s + 1, dydx = s1 >> 2, ci0 = (s1 & 3) * 64;
            int dy = dydx / 9, dx = dydx - dy * 9;
            uint32_t stepA = (uint32_t)(((dy * 20 + dx) * 256 + ci0) * 2);
            uint32_t stepB = (uint32_t)(((dydx * 256 + ci0) * 256) * 2);
            uint32_t ba = smb + (uint32_t)((s1 & 1) ? C2_BUFSZ : 0u);
            for (int i = 0; i < an; i++) {
                cp16(ba + C2_AHI + adst[i], hh + asrc[i] + stepA);
                cp16(ba + C2_ALO + adst[i], hl + asrc[i] + stepA);
            }
#pragma unroll
            for (int i = 0; i < 4; i++) {
                cp16(ba + C2_BHI + bdst0 + i * 8448u, wh + bsrc0 + stepB + i * 8192u);
                cp16(ba + C2_BLO + bdst0 + i * 8448u, wl + bsrc0 + stepB + i * 8192u);
            }
            cp_commit();
        }
        uint32_t base = smb + (uint32_t)((s & 1) ? C2_BUFSZ : 0u);
        uint32_t Ah = base + C2_AHI, Al = base + C2_ALO;
        uint32_t Bh = base + C2_BHI, Bl = base + C2_BLO;
#pragma unroll
        for (int kk = 0; kk < 4; kk++) {
            uint32_t bh[4], bl[4];
            uint32_t bo = (uint32_t)(kk * 16 * 528) + brow;
            ldsm4t(bh, Bh + bo);
            ldsm4t(bl, Bl + bo);
#pragma unroll
            for (int mt = 0; mt < 9; mt++) {
                uint32_t ah[4], al[4];
                uint32_t ao = (uint32_t)(mt * 16 * 144 + kk * 32) + arow;
                ldsm4(ah, Ah + ao);
                ldsm4(al, Al + ao);
                mma16816(acc[mt][0], ah, bh);
                mma16816(acc[mt][1], ah, bh + 2);
                mma16816(acc[mt][0], ah, bl);
                mma16816(acc[mt][1], ah, bl + 2);
                mma16816(acc[mt][0], al, bh);
                mma16816(acc[mt][1], al, bh + 2);
            }
        }
    }

    // ---- fused epilogue: bias add -> smem [img][p][m][9] -> squash -> g_u ----
    __syncthreads();                       // everyone done with step 323's buffer
    float* S = (float*)smc;                // 4*36*32*9 floats = 165888 B
    int gid = T >> 2, tig = T & 3;
#pragma unroll
    for (int nt = 0; nt < 2; nt++) {
        int oc0 = w * 16 + nt * 8 + tig * 2;
        int oc1 = oc0 + 1;
        float bv0 = bias[oc0], bv1 = bias[oc1];
        int off0 = (oc0 & 31) * 9 + (oc0 >> 5);
        int off1 = (oc1 & 31) * 9 + (oc1 >> 5);
#pragma unroll
        for (int mt = 0; mt < 9; mt++) {
#pragma unroll
            for (int h = 0; h < 2; h++) {
                int row = mt * 16 + gid + h * 8;
                int img = row / 36, p = row - img * 36;
                int base = (img * 36 + p) * 288;   // 32*9
                S[base + off0] = acc[mt][nt][h * 2 + 0] + bv0;
                S[base + off1] = acc[mt][nt][h * 2 + 1] + bv1;
            }
        }
    }
    __syncthreads();
#pragma unroll
    for (int k = 0; k < 9; k++) {
        int c = t + k * 512;                // 4608 capsules: c = img*1152 + r, r = m*36+p
        int img = c / 1152;
        int r = c - img * 1152;
        int m = r / 36, p = r - m * 36;
        const float* sp = S + (img * 36 + p) * 288 + m * 9;
        float v0 = sp[0], v1 = sp[1], v2 = sp[2], v3 = sp[3];
        float v4 = sp[4], v5 = sp[5], v6 = sp[6], v7 = sp[7];
        float sq = v0*v0 + v1*v1 + v2*v2 + v3*v3 + v4*v4 + v5*v5 + v6*v6 + v7*v7;
        float sc = sq / ((1.f + sq) * sqrtf(sq));
        float4* dst = (float4*)(g_u + ((size_t)(bq * 4 + img) * 1152 + r) * 8);
        dst[0] = make_float4(v0 * sc, v1 * sc, v2 * sc, v3 * sc);
        dst[1] = make_float4(v4 * sc, v5 * sc, v6 * sc, v7 * sc);
    }
}

// ---------------- routing: block = (class, image), 288 threads x 4 consecutive routes ----------
// route_w loads are float4 (transposed layout), u loads are float4. 2 CTAs/SM. (R11 config)
__global__ __launch_bounds__(288, 2) void routing_kernel() {
    __shared__ float red[9][17];
    __shared__ float mred[9];
    int c = blockIdx.x, b = blockIdx.y, t = threadIdx.x;
    int lane = t & 31, wid = t >> 5;
    const float4* w4 = (const float4*)(g_rw2 + (size_t)c * 147456);
    const float4* up = (const float4*)(g_u + (size_t)b * 9216 + (size_t)t * 32);

    // u values for 4 consecutive routes (4t .. 4t+3)
    float uu[4][8];
#pragma unroll
    for (int j = 0; j < 4; j++) {
        float4 a = up[j * 2], bb = up[j * 2 + 1];
        uu[j][0] = a.x; uu[j][1] = a.y; uu[j][2] = a.z; uu[j][3] = a.w;
        uu[j][4] = bb.x; uu[j][5] = bb.y; uu[j][6] = bb.z; uu[j][7] = bb.w;
    }

    float pr[4][16];
#pragma unroll
    for (int j = 0; j < 4; j++)
#pragma unroll
        for (int o = 0; o < 16; o++) pr[j][o] = 0.f;

#pragma unroll
    for (int i = 0; i < 8; i++) {
#pragma unroll
        for (int o = 0; o < 16; o++) {
            float4 wv = w4[(size_t)(i * 16 + o) * 288 + t];
            pr[0][o] = fmaf(uu[0][i], wv.x, pr[0][o]);
            pr[1][o] = fmaf(uu[1][i], wv.y, pr[1][o]);
            pr[2][o] = fmaf(uu[2][i], wv.z, pr[2][o]);
            pr[3][o] = fmaf(uu[3][i], wv.w, pr[3][o]);
        }
    }

    float lg[4] = {0.f, 0.f, 0.f, 0.f};
    float s[16];
    for (int it = 0; it < 3; it++) {
        // block max of logits
        float mx = fmaxf(fmaxf(lg[0], lg[1]), fmaxf(lg[2], lg[3]));
#pragma unroll
        for (int off = 16; off; off >>= 1) mx = fmaxf(mx, __shfl_xor_sync(0xffffffffu, mx, off));
        if (lane == 0) mred[wid] = mx;
        __syncthreads();
        float M = mred[0];
#pragma unroll
        for (int ww = 1; ww < 9; ww++) M = fmaxf(M, mred[ww]);

        // weighted sums
#pragma unroll
        for (int o = 0; o < 16; o++) s[o] = 0.f;
        float z = 0.f;
#pragma unroll
        for (int j = 0; j < 4; j++) {
            float e = expf(lg[j] - M);
            z += e;
#pragma unroll
            for (int o = 0; o < 16; o++) s[o] = fmaf(e, pr[j][o], s[o]);
        }
#pragma unroll
        for (int off = 16; off; off >>= 1) {
            z += __shfl_xor_sync(0xffffffffu, z, off);
#pragma unroll
            for (int o = 0; o < 16; o++) s[o] += __shfl_xor_sync(0xffffffffu, s[o], off);
        }
        if (lane == 0) {
#pragma unroll
            for (int o = 0; o < 16; o++) red[wid][o] = s[o];
            red[wid][16] = z;
        }
        __syncthreads();
        float Z = 0.f;
#pragma unroll
        for (int o = 0; o < 16; o++) s[o] = 0.f;
#pragma unroll
        for (int ww = 0; ww < 9; ww++) {
            Z += red[ww][16];
#pragma unroll
            for (int o = 0; o < 16; o++) s[o] += red[ww][o];
        }
        float q = 0.f;
#pragma unroll
        for (int o = 0; o < 16; o++) { s[o] /= Z; q = fmaf(s[o], s[o], q); }
        float sc = q / ((1.f + q) * sqrtf(q));
#pragma unroll
        for (int o = 0; o < 16; o++) s[o] *= sc;
        if (it < 2) {
#pragma unroll
            for (int j = 0; j < 4; j++) {
                float d = 0.f;
#pragma unroll
                for (int o = 0; o < 16; o++) d = fmaf(pr[j][o], s[o], d);
                lg[j] += d;
            }
        }
        __syncthreads();   // protect red/mred before next iteration's writes
    }
    if (t == 0) {
        float* cp = g_caps + ((size_t)b * NC + c) * 16;
#pragma unroll
        for (int o = 0; o < 16; o++) cp[o] = s[o];
    }
}

// ---------------- classes softmax + argmax -> compact decoder input ----------------
__global__ void classes_kernel(float* __restrict__ out_classes) {
    int b = blockIdx.x, lane = threadIdx.x;  // 32 threads
    float n2 = 0.f;
    if (lane < NC) {
        const float* cp = g_caps + ((size_t)b * NC + lane) * 16;
#pragma unroll
        for (int o = 0; o < 16; o++) n2 = fmaf(cp[o], cp[o], n2);
    }
    float nrm = (lane < NC) ? sqrtf(n2) : -3.0e38f;
    float mx = nrm;
#pragma unroll
    for (int off = 16; off; off >>= 1) mx = fmaxf(mx, __shfl_xor_sync(0xffffffffu, mx, off));
    float e = (lane < NC) ? expf(nrm - mx) : 0.f;
    float zz = e;
#pragma unroll
    for (int off = 16; off; off >>= 1) zz += __shfl_xor_sync(0xffffffffu, zz, off);
    if (lane < NC) out_classes[b * NC + lane] = e / zz;
    unsigned msk = __ballot_sync(0xffffffffu, nrm == mx);
    int am = __ffs(msk) - 1;   // first (lowest-index) max, matches jnp.argmax
    const float* ap = g_caps + ((size_t)b * NC + am) * 16;
    if (lane < 16) g_c16[b * 16 + lane] = ap[lane];
    if (lane == 0) g_am[b] = am;
}

// ---------------- sparse decoder layer 1: d1 = relu(W1[:, am*16 : am*16+16] @ c16 + b1) ------
__global__ __launch_bounds__(256) void gemm1s_kernel(const float* __restrict__ W1,
                                                     const float* __restrict__ b1v,
                                                     float* __restrict__ d1) {
    int idx = blockIdx.x * 256 + threadIdx.x;   // 512*512 outputs
    int row = idx >> 9, n = idx & 511;
    int am = g_am[row];
    const float4* wp = (const float4*)(W1 + (size_t)n * 160 + am * 16);
    const float4* cp = (const float4*)(g_c16 + row * 16);
    float acc = 0.f;
#pragma unroll
    for (int q = 0; q < 4; q++) {
        float4 wv = wp[q], cv = cp[q];
        acc = fmaf(wv.x, cv.x, acc);
        acc = fmaf(wv.y, cv.y, acc);
        acc = fmaf(wv.z, cv.z, acc);
        acc = fmaf(wv.w, cv.w, acc);
    }
    d1[idx] = fmaxf(acc + b1v[n], 0.f);
}

// ---------------- decoder GEMM (FFMA2): C[512,N] = act(A[512,K] @ W[N,K]^T + bias) ----------
// As stored kk-major [32][66] (even stride -> 8B-aligned float2 row-pair loads, broadcast
// reads). Per-lane fma order identical to the scalar version -> bit-identical results.
__global__ __launch_bounds__(256) void gemm_kernel(const float* __restrict__ A,
                                                   const float* __restrict__ W,
                                                   const float* __restrict__ bias,
                                                   float* __restrict__ C,
                                                   int N, int K, int act) {
    __shared__ float As[32][66];   // [kk][mm]
    __shared__ float Bs[64][33];   // [n][kk]
    int tx = threadIdx.x & 15, ty = threadIdx.x >> 4;
    int m0 = blockIdx.y * 64, n0 = blockIdx.x * 64;
    float2 acc[2][4];
#pragma unroll
    for (int p = 0; p < 2; p++)
#pragma unroll
        for (int j = 0; j < 4; j++) acc[p][j] = make_float2(0.f, 0.f);
    for (int k0 = 0; k0 < K; k0 += 32) {
        __syncthreads();
        for (int idx = threadIdx.x; idx < 2048; idx += 256) {
            int mm = idx >> 5, kk = idx & 31;
            As[kk][mm] = A[(size_t)(m0 + mm) * K + k0 + kk];
            Bs[mm][kk] = (n0 + mm < N) ? W[(size_t)(n0 + mm) * K + k0 + kk] : 0.f;
        }
        __syncthreads();
#pragma unroll
        for (int kk = 0; kk < 32; kk++) {
            float2 a0 = *(const float2*)&As[kk][ty * 4];
            float2 a1 = *(const float2*)&As[kk][ty * 4 + 2];
#pragma unroll
            for (int j = 0; j < 4; j++) {
                float bv = Bs[tx * 4 + j][kk];
                float2 b2 = make_float2(bv, bv);
                ffma2(acc[0][j], a0, b2);
                ffma2(acc[1][j], a1, b2);
            }
        }
    }
#pragma unroll
    for (int p = 0; p < 2; p++) {
        int cm0 = m0 + ty * 4 + p * 2;
#pragma unroll
        for (int j = 0; j < 4; j++) {
            int cn = n0 + tx * 4 + j;
            if (cn < N) {
                float bv = bias[cn];
                float v0 = acc[p][j].x + bv;
                float v1 = acc[p][j].y + bv;
                v0 = act ? (1.f / (1.f + expf(-v0))) : fmaxf(v0, 0.f);
                v1 = act ? (1.f / (1.f + expf(-v1))) : fmaxf(v1, 0.f);
                C[(size_t)cm0 * N + cn] = v0;
                C[(size_t)(cm0 + 1) * N + cn] = v1;
            }
        }
    }
}

extern "C" void kernel_launch(void* const* d_in, const int* in_sizes, int n_in,
                              void* d_out, int out_size) {
    const float* x   = (const float*)d_in[0];
    const float* c1w = (const float*)d_in[1];
    const float* c1b = (const float*)d_in[2];
    const float* pw  = (const float*)d_in[3];
    const float* pb  = (const float*)d_in[4];
    const float* rw  = (const float*)d_in[5];
    const float* w1  = (const float*)d_in[6];
    const float* b1  = (const float*)d_in[7];
    const float* w2  = (const float*)d_in[8];
    const float* b2  = (const float*)d_in[9];
    const float* w3  = (const float*)d_in[10];
    const float* b3  = (const float*)d_in[11];
    float* out = (float*)d_out;
    float* out_classes = out;              // [512,10]
    float* out_recon   = out + 512 * NC;   // [512,784]

    void *p_d1, *p_d2;
    cudaGetSymbolAddress(&p_d1, g_d1);
    cudaGetSymbolAddress(&p_d2, g_d2);

    prep_w_kernel<<<256, 256>>>(pw);                    // launch 1
    prep_rw_kernel<<<dim3(36, 4, 10), 256>>>(rw);       // launch 2
    conv1_kernel<<<dim3(8, 256), 640>>>(x, c1w, c1b);   // launch 3

    int c2sm = 2 * C2_BUFSZ;  // 218112 B
    cudaFuncSetAttribute(conv2_mma_kernel, cudaFuncAttributeMaxDynamicSharedMemorySize, c2sm);
    conv2_mma_kernel<<<128, 512, c2sm>>>(pb);           // launch 4 (profiled slot)

    routing_kernel<<<dim3(10, 512), 288>>>();

    classes_kernel<<<512, 32>>>(out_classes);

    gemm1s_kernel<<<1024, 256>>>(w1, b1, (float*)p_d1);
    gemm_kernel<<<dim3(16, 8), 256>>>((const float*)p_d1, w2, b2, (float*)p_d2, 1024, 512, 0);
    gemm_kernel<<<dim3(13, 8), 256>>>((const float*)p_d2, w3, b3, out_recon, 784, 1024, 1);
}

// round 17
// speedup vs baseline: 1.5830x; 1.0094x over previous
#include <cuda_runtime.h>
#include <cuda_bf16.h>
#include <math.h>
#include <stdint.h>

#define NC 10

// ---------------- scratch (static device arrays; no runtime allocation) ----------------
__device__ __nv_bfloat16 g_hh[52428800];  // [512 b][20 y][20 x][256 c] conv1 out, bf16 hi
__device__ __nv_bfloat16 g_hl[52428800];  // same, bf16 lo (residual)
__device__ __nv_bfloat16 g_wh[5308416];   // [81 dydx][256 ci][256 oc] weights hi
__device__ __nv_bfloat16 g_wl[5308416];   // weights lo
__device__ float g_rw2[1474560];          // [10 c][128 io][1152 r] transposed route_w
__device__ float g_u[4718592];            // [512][1152][8] primary capsules (squashed)
__device__ float g_caps[81920];           // [512][10][16]
__device__ int   g_am[512];               // argmax class per image
__device__ float g_c16[8192];             // [512][16] winning capsule
__device__ float g_d1[262144];            // [512][512]
__device__ float g_d2[524288];            // [512][1024]

// ---------------- PTX helpers (all baseline sm_80+; no arch-'a' features) ----------------
__device__ __forceinline__ void ffma2(float2& c, const float2 a, const float2 b) {
    asm("fma.rn.f32x2 %0, %1, %2, %0;"
        : "+l"(reinterpret_cast<unsigned long long&>(c))
        : "l"(reinterpret_cast<const unsigned long long&>(a)),
          "l"(reinterpret_cast<const unsigned long long&>(b)));
}
__device__ __forceinline__ void cp16(uint32_t d, const void* s) {
    asm volatile("cp.async.cg.shared.global [%0], [%1], 16;" :: "r"(d), "l"(s));
}
__device__ __forceinline__ void cp4(uint32_t d, const void* s) {
    asm volatile("cp.async.ca.shared.global [%0], [%1], 4;" :: "r"(d), "l"(s));
}
__device__ __forceinline__ void cp_commit() { asm volatile("cp.async.commit_group;"); }
__device__ __forceinline__ void cp_wait0()  { asm volatile("cp.async.wait_group 0;" ::: "memory"); }

__device__ __forceinline__ void ldsm4(uint32_t* r, uint32_t addr) {
    asm volatile("ldmatrix.sync.aligned.m8n8.x4.shared.b16 {%0,%1,%2,%3}, [%4];"
        : "=r"(r[0]), "=r"(r[1]), "=r"(r[2]), "=r"(r[3]) : "r"(addr));
}
__device__ __forceinline__ void ldsm4t(uint32_t* r, uint32_t addr) {
    asm volatile("ldmatrix.sync.aligned.m8n8.x4.trans.shared.b16 {%0,%1,%2,%3}, [%4];"
        : "=r"(r[0]), "=r"(r[1]), "=r"(r[2]), "=r"(r[3]) : "r"(addr));
}
__device__ __forceinline__ void mma16816(float* c, const uint32_t* a, const uint32_t* b) {
    asm volatile("mma.sync.aligned.m16n8k16.row.col.f32.bf16.bf16.f32 "
        "{%0,%1,%2,%3}, {%4,%5,%6,%7}, {%8,%9}, {%0,%1,%2,%3};"
        : "+f"(c[0]), "+f"(c[1]), "+f"(c[2]), "+f"(c[3])
        : "r"(a[0]), "r"(a[1]), "r"(a[2]), "r"(a[3]), "r"(b[0]), "r"(b[1]));
}

// ---------------- prep (merged): weights -> [dydx][ci][oc] hi/lo; route_w transpose ----------
__global__ __launch_bounds__(256) void prep_kernel(const float* __restrict__ pw,
                                                   const float* __restrict__ rw) {
    int blk = blockIdx.x;
    if (blk < 256) {
        int idx = blk * 256 + threadIdx.x;   // 65536 = ci*256 + oc
        int ci = idx >> 8, oc = idx & 255;
        const float* src = pw + (size_t)(oc * 256 + ci) * 81;
#pragma unroll 3
        for (int k = 0; k < 81; k++) {
            float w = src[k];
            __nv_bfloat16 hi = __float2bfloat16(w);
            __nv_bfloat16 lo = __float2bfloat16(w - __bfloat162float(hi));
            size_t o = ((size_t)k * 256 + ci) * 256 + oc;
            g_wh[o] = hi;
            g_wl[o] = lo;
        }
    } else {
        __shared__ float tile[32][33];
        int z = blk - 256;                   // 0..1439
        int rb = z % 36, iob = (z / 36) & 3, c = z / 144;
        int tx = threadIdx.x & 31, ty = threadIdx.x >> 5;   // ty 0..7
#pragma unroll
        for (int k = 0; k < 4; k++) {
            int r = rb * 32 + ty * 4 + k;
            tile[ty * 4 + k][tx] = rw[((size_t)c * 1152 + r) * 128 + iob * 32 + tx];
        }
        __syncthreads();
#pragma unroll
        for (int k = 0; k < 4; k++) {
            int io = iob * 32 + ty * 4 + k;
            g_rw2[((size_t)c * 128 + io) * 1152 + rb * 32 + tx] = tile[tx][ty * 4 + k];
        }
    }
}

// ---------------- conv1: 2 images/block via FFMA2 -> relu -> NHWC bf16 hi/lo ----------------
__global__ __launch_bounds__(640) void conv1_kernel(const float* __restrict__ x,
                                                    const float* __restrict__ w,
                                                    const float* __restrict__ bias) {
    __shared__ __align__(16) float2 img2[784];
    __shared__ float ws[2592];
    __shared__ float bs[32];
    int bp = blockIdx.y, ocg = blockIdx.x, t = threadIdx.x;
    const float* x0 = x + (size_t)(bp * 2) * 784;
    const float* x1 = x0 + 784;
    for (int i = t; i < 784; i += 640) img2[i] = make_float2(x0[i], x1[i]);
    for (int i = t; i < 2592; i += 640) ws[i] = w[(size_t)ocg * 2592 + i];
    if (t < 32) bs[t] = bias[ocg * 32 + t];
    __syncthreads();
    int oc = t & 31, y = t >> 5;
    float2 acc[20];
#pragma unroll
    for (int i = 0; i < 20; i++) acc[i] = make_float2(0.f, 0.f);
    for (int dy = 0; dy < 9; dy++) {
        const float2* rp = img2 + (y + dy) * 28;
        const float* wrow = ws + oc * 81 + dy * 9;
#pragma unroll
        for (int q = 0; q < 4; q++) {          // xo quarters of 5, cols q*5 .. q*5+12
            float2 r[14];
#pragma unroll
            for (int i = 0; i < 14; i++) r[i] = rp[q * 5 + i];
#pragma unroll
            for (int dx = 0; dx < 9; dx++) {
                float wv = wrow[dx];
                float2 w2 = make_float2(wv, wv);
#pragma unroll
                for (int xo = 0; xo < 5; xo++)
                    ffma2(acc[q * 5 + xo], w2, r[xo + dx]);
            }
        }
    }
    float bv = bs[oc];
    size_t base0 = (((size_t)(bp * 2) * 20 + y) * 20) * 256 + ocg * 32 + oc;
    size_t base1 = base0 + (size_t)400 * 256;
#pragma unroll
    for (int i = 0; i < 20; i++) {
        float v0 = fmaxf(acc[i].x + bv, 0.f);
        float v1 = fmaxf(acc[i].y + bv, 0.f);
        __nv_bfloat16 h0 = __float2bfloat16(v0);
        __nv_bfloat16 h1 = __float2bfloat16(v1);
        g_hh[base0 + (size_t)i * 256] = h0;
        g_hl[base0 + (size_t)i * 256] = __float2bfloat16(v0 - __bfloat162float(h0));
        g_hh[base1 + (size_t)i * 256] = h1;
        g_hl[base1 + (size_t)i * 256] = __float2bfloat16(v1 - __bfloat162float(h1));
    }
}

// ---------------- conv2 via mma.sync bf16 (hi/lo, 3 passes) + fused bias/squash ----------------
// R7 tiling (proven ceiling for this path): 512 thr / 16 warps, warp w owns N=16, 9 m-tiles.
// Single __syncthreads per step: [wait0; sync; stage s+1; compute s].
#define C2_AHI   0u
#define C2_ALO   20736u
#define C2_BHI   41472u
#define C2_BLO   75264u
#define C2_BUFSZ 109056u
#define C2_STEPS 324

__global__ __launch_bounds__(512, 1) void conv2_mma_kernel(const float* __restrict__ bias) {
    extern __shared__ __align__(16) char smc[];
    uint32_t smb = (uint32_t)__cvta_generic_to_shared(smc);
    int t = threadIdx.x;
    int bq = blockIdx.x;
    int w = t >> 5, T = t & 31;

    // A staging descriptors
    uint32_t asrc[3], adst[3]; int an = 0;
#pragma unroll
    for (int i = 0; i < 3; i++) {
        int idx = t + i * 512;
        if (idx < 1152) {
            int row = idx >> 3, c = idx & 7;
            int img = row / 36, p = row - img * 36, oy = p / 6, ox = p - oy * 6;
            asrc[an] = (uint32_t)((((long)(bq * 4 + img) * 400 + (long)(2 * oy) * 20 + 2 * ox) * 256 + c * 8) * 2);
            adst[an] = (uint32_t)(row * 144 + c * 16);
            an++;
        }
    }
    // B staging: affine in i (idx += 512 -> row += 16)
    uint32_t bsrc0, bdst0;
    {
        int row = t >> 5, c = t & 31;
        bsrc0 = (uint32_t)((row * 256 + c * 8) * 2);   // += 8192 per i
        bdst0 = (uint32_t)(row * 528 + c * 16);        // += 8448 per i
    }
    const char* hh = (const char*)g_hh;
    const char* hl = (const char*)g_hl;
    const char* wh = (const char*)g_wh;
    const char* wl = (const char*)g_wl;

    // prologue: stage step 0 into buffer 0
    {
        uint32_t ba = smb;
        for (int i = 0; i < an; i++) {
            cp16(ba + C2_AHI + adst[i], hh + asrc[i]);
            cp16(ba + C2_ALO + adst[i], hl + asrc[i]);
        }
#pragma unroll
        for (int i = 0; i < 4; i++) {
            cp16(ba + C2_BHI + bdst0 + i * 8448u, wh + bsrc0 + i * 8192u);
            cp16(ba + C2_BLO + bdst0 + i * 8448u, wl + bsrc0 + i * 8192u);
        }
        cp_commit();
    }

    float acc[9][2][4];
#pragma unroll
    for (int m = 0; m < 9; m++)
#pragma unroll
        for (int n = 0; n < 2; n++)
#pragma unroll
            for (int i = 0; i < 4; i++) acc[m][n][i] = 0.f;

    uint32_t arow = (uint32_t)((T & 15) * 144 + ((T & 16) ? 16 : 0));
    uint32_t brow = (uint32_t)((T & 15) * 528 + w * 32 + ((T & 16) ? 16 : 0));

    for (int s = 0; s < C2_STEPS; s++) {
        cp_wait0();          // step-s data arrived
        __syncthreads();     // all warps done reading buf[(s+1)&1] (step s-1)
        if (s + 1 < C2_STEPS) {
            int s1 = s + 1, dydx = s1 >> 2, ci0 = (s1 & 3) * 64;
            int dy = dydx / 9, dx = dydx - dy * 9;
            uint32_t stepA = (uint32_t)(((dy * 20 + dx) * 256 + ci0) * 2);
            uint32_t stepB = (uint32_t)(((dydx * 256 + ci0) * 256) * 2);
            uint32_t ba = smb + (uint32_t)((s1 & 1) ? C2_BUFSZ : 0u);
            for (int i = 0; i < an; i++) {
                cp16(ba + C2_AHI + adst[i], hh + asrc[i] + stepA);
                cp16(ba + C2_ALO + adst[i], hl + asrc[i] + stepA);
            }
#pragma unroll
            for (int i = 0; i < 4; i++) {
                cp16(ba + C2_BHI + bdst0 + i * 8448u, wh + bsrc0 + stepB + i * 8192u);
                cp16(ba + C2_BLO + bdst0 + i * 8448u, wl + bsrc0 + stepB + i * 8192u);
            }
            cp_commit();
        }
        uint32_t base = smb + (uint32_t)((s & 1) ? C2_BUFSZ : 0u);
        uint32_t Ah = base + C2_AHI, Al = base + C2_ALO;
        uint32_t Bh = base + C2_BHI, Bl = base + C2_BLO;
#pragma unroll
        for (int kk = 0; kk < 4; kk++) {
            uint32_t bh[4], bl[4];
            uint32_t bo = (uint32_t)(kk * 16 * 528) + brow;
            ldsm4t(bh, Bh + bo);
            ldsm4t(bl, Bl + bo);
#pragma unroll
            for (int mt = 0; mt < 9; mt++) {
                uint32_t ah[4], al[4];
                uint32_t ao = (uint32_t)(mt * 16 * 144 + kk * 32) + arow;
                ldsm4(ah, Ah + ao);
                ldsm4(al, Al + ao);
                mma16816(acc[mt][0], ah, bh);
                mma16816(acc[mt][1], ah, bh + 2);
                mma16816(acc[mt][0], ah, bl);
                mma16816(acc[mt][1], ah, bl + 2);
                mma16816(acc[mt][0], al, bh);
                mma16816(acc[mt][1], al, bh + 2);
            }
        }
    }

    // ---- fused epilogue: bias add -> smem [img][p][m][9] -> squash -> g_u ----
    __syncthreads();                       // everyone done with step 323's buffer
    float* S = (float*)smc;                // 4*36*32*9 floats = 165888 B
    int gid = T >> 2, tig = T & 3;
#pragma unroll
    for (int nt = 0; nt < 2; nt++) {
        int oc0 = w * 16 + nt * 8 + tig * 2;
        int oc1 = oc0 + 1;
        float bv0 = bias[oc0], bv1 = bias[oc1];
        int off0 = (oc0 & 31) * 9 + (oc0 >> 5);
        int off1 = (oc1 & 31) * 9 + (oc1 >> 5);
#pragma unroll
        for (int mt = 0; mt < 9; mt++) {
#pragma unroll
            for (int h = 0; h < 2; h++) {
                int row = mt * 16 + gid + h * 8;
                int img = row / 36, p = row - img * 36;
                int base = (img * 36 + p) * 288;   // 32*9
                S[base + off0] = acc[mt][nt][h * 2 + 0] + bv0;
                S[base + off1] = acc[mt][nt][h * 2 + 1] + bv1;
            }
        }
    }
    __syncthreads();
#pragma unroll
    for (int k = 0; k < 9; k++) {
        int c = t + k * 512;                // 4608 capsules: c = img*1152 + r, r = m*36+p
        int img = c / 1152;
        int r = c - img * 1152;
        int m = r / 36, p = r - m * 36;
        const float* sp = S + (img * 36 + p) * 288 + m * 9;
        float v0 = sp[0], v1 = sp[1], v2 = sp[2], v3 = sp[3];
        float v4 = sp[4], v5 = sp[5], v6 = sp[6], v7 = sp[7];
        float sq = v0*v0 + v1*v1 + v2*v2 + v3*v3 + v4*v4 + v5*v5 + v6*v6 + v7*v7;
        float sc = sq / ((1.f + sq) * sqrtf(sq));
        float4* dst = (float4*)(g_u + ((size_t)(bq * 4 + img) * 1152 + r) * 8);
        dst[0] = make_float4(v0 * sc, v1 * sc, v2 * sc, v3 * sc);
        dst[1] = make_float4(v4 * sc, v5 * sc, v6 * sc, v7 * sc);
    }
}

// ---------------- routing: block = (image fastest, class slow) for co-resident CTA locality --
// Same-class CTAs co-resident on an SM stream identical route_w addresses -> L1/L2 reuse.
__global__ __launch_bounds__(288, 2) void routing_kernel() {
    __shared__ float red[9][17];
    __shared__ float mred[9];
    int b = blockIdx.x, c = blockIdx.y, t = threadIdx.x;
    int lane = t & 31, wid = t >> 5;
    const float4* w4 = (const float4*)(g_rw2 + (size_t)c * 147456);
    const float4* up = (const float4*)(g_u + (size_t)b * 9216 + (size_t)t * 32);

    // u values for 4 consecutive routes (4t .. 4t+3)
    float uu[4][8];
#pragma unroll
    for (int j = 0; j < 4; j++) {
        float4 a = up[j * 2], bb = up[j * 2 + 1];
        uu[j][0] = a.x; uu[j][1] = a.y; uu[j][2] = a.z; uu[j][3] = a.w;
        uu[j][4] = bb.x; uu[j][5] = bb.y; uu[j][6] = bb.z; uu[j][7] = bb.w;
    }

    float pr[4][16];
#pragma unroll
    for (int j = 0; j < 4; j++)
#pragma unroll
        for (int o = 0; o < 16; o++) pr[j][o] = 0.f;

#pragma unroll
    for (int i = 0; i < 8; i++) {
#pragma unroll
        for (int o = 0; o < 16; o++) {
            float4 wv = w4[(size_t)(i * 16 + o) * 288 + t];
            pr[0][o] = fmaf(uu[0][i], wv.x, pr[0][o]);
            pr[1][o] = fmaf(uu[1][i], wv.y, pr[1][o]);
            pr[2][o] = fmaf(uu[2][i], wv.z, pr[2][o]);
            pr[3][o] = fmaf(uu[3][i], wv.w, pr[3][o]);
        }
    }

    float lg[4] = {0.f, 0.f, 0.f, 0.f};
    float s[16];
    for (int it = 0; it < 3; it++) {
        // block max of logits
        float mx = fmaxf(fmaxf(lg[0], lg[1]), fmaxf(lg[2], lg[3]));
#pragma unroll
        for (int off = 16; off; off >>= 1) mx = fmaxf(mx, __shfl_xor_sync(0xffffffffu, mx, off));
        if (lane == 0) mred[wid] = mx;
        __syncthreads();
        float M = mred[0];
#pragma unroll
        for (int ww = 1; ww < 9; ww++) M = fmaxf(M, mred[ww]);

        // weighted sums
#pragma unroll
        for (int o = 0; o < 16; o++) s[o] = 0.f;
        float z = 0.f;
#pragma unroll
        for (int j = 0; j < 4; j++) {
            float e = expf(lg[j] - M);
            z += e;
#pragma unroll
            for (int o = 0; o < 16; o++) s[o] = fmaf(e, pr[j][o], s[o]);
        }
#pragma unroll
        for (int off = 16; off; off >>= 1) {
            z += __shfl_xor_sync(0xffffffffu, z, off);
#pragma unroll
            for (int o = 0; o < 16; o++) s[o] += __shfl_xor_sync(0xffffffffu, s[o], off);
        }
        if (lane == 0) {
#pragma unroll
            for (int o = 0; o < 16; o++) red[wid][o] = s[o];
            red[wid][16] = z;
        }
        __syncthreads();
        float Z = 0.f;
#pragma unroll
        for (int o = 0; o < 16; o++) s[o] = 0.f;
#pragma unroll
        for (int ww = 0; ww < 9; ww++) {
            Z += red[ww][16];
#pragma unroll
            for (int o = 0; o < 16; o++) s[o] += red[ww][o];
        }
        float q = 0.f;
#pragma unroll
        for (int o = 0; o < 16; o++) { s[o] /= Z; q = fmaf(s[o], s[o], q); }
        float sc = q / ((1.f + q) * sqrtf(q));
#pragma unroll
        for (int o = 0; o < 16; o++) s[o] *= sc;
        if (it < 2) {
#pragma unroll
            for (int j = 0; j < 4; j++) {
                float d = 0.f;
#pragma unroll
                for (int o = 0; o < 16; o++) d = fmaf(pr[j][o], s[o], d);
                lg[j] += d;
            }
        }
        __syncthreads();   // protect red/mred before next iteration's writes
    }
    if (t == 0) {
        float* cp = g_caps + ((size_t)b * NC + c) * 16;
#pragma unroll
        for (int o = 0; o < 16; o++) cp[o] = s[o];
    }
}

// ---------------- classes softmax + argmax -> compact decoder input ----------------
__global__ void classes_kernel(float* __restrict__ out_classes) {
    int b = blockIdx.x, lane = threadIdx.x;  // 32 threads
    float n2 = 0.f;
    if (lane < NC) {
        const float* cp = g_caps + ((size_t)b * NC + lane) * 16;
#pragma unroll
        for (int o = 0; o < 16; o++) n2 = fmaf(cp[o], cp[o], n2);
    }
    float nrm = (lane < NC) ? sqrtf(n2) : -3.0e38f;
    float mx = nrm;
#pragma unroll
    for (int off = 16; off; off >>= 1) mx = fmaxf(mx, __shfl_xor_sync(0xffffffffu, mx, off));
    float e = (lane < NC) ? expf(nrm - mx) : 0.f;
    float zz = e;
#pragma unroll
    for (int off = 16; off; off >>= 1) zz += __shfl_xor_sync(0xffffffffu, zz, off);
    if (lane < NC) out_classes[b * NC + lane] = e / zz;
    unsigned msk = __ballot_sync(0xffffffffu, nrm == mx);
    int am = __ffs(msk) - 1;   // first (lowest-index) max, matches jnp.argmax
    const float* ap = g_caps + ((size_t)b * NC + am) * 16;
    if (lane < 16) g_c16[b * 16 + lane] = ap[lane];
    if (lane == 0) g_am[b] = am;
}

// ---------------- sparse decoder layer 1: d1 = relu(W1[:, am*16 : am*16+16] @ c16 + b1) ------
__global__ __launch_bounds__(256) void gemm1s_kernel(const float* __restrict__ W1,
                                                     const float* __restrict__ b1v,
                                                     float* __restrict__ d1) {
    int idx = blockIdx.x * 256 + threadIdx.x;   // 512*512 outputs
    int row = idx >> 9, n = idx & 511;
    int am = g_am[row];
    const float4* wp = (const float4*)(W1 + (size_t)n * 160 + am * 16);
    const float4* cp = (const float4*)(g_c16 + row * 16);
    float acc = 0.f;
#pragma unroll
    for (int q = 0; q < 4; q++) {
        float4 wv = wp[q], cv = cp[q];
        acc = fmaf(wv.x, cv.x, acc);
        acc = fmaf(wv.y, cv.y, acc);
        acc = fmaf(wv.z, cv.z, acc);
        acc = fmaf(wv.w, cv.w, acc);
    }
    d1[idx] = fmaxf(acc + b1v[n], 0.f);
}

// ---------------- decoder GEMM (FFMA2, cp.async double-buffered) ----------------------------
// As kk-major [32][66]; Bs [64][33]. OOB Bs rows pre-zeroed once and never written by cp.async.
// Loop: [wait0; sync; stage k+1; compute k] (proven conv2 pattern). Values/order identical.
__global__ __launch_bounds__(256) void gemm_kernel(const float* __restrict__ A,
                                                   const float* __restrict__ W,
                                                   const float* __restrict__ bias,
                                                   float* __restrict__ C,
                                                   int N, int K, int act) {
    __shared__ float As[2][32][66];
    __shared__ float Bs[2][64][33];
    uint32_t as_b = (uint32_t)__cvta_generic_to_shared(&As[0][0][0]);
    uint32_t bs_b = (uint32_t)__cvta_generic_to_shared(&Bs[0][0][0]);
    const uint32_t AS_SZ = 32 * 66 * 4, BS_SZ = 64 * 33 * 4;
    int tx = threadIdx.x & 15, ty = threadIdx.x >> 4;
    int m0 = blockIdx.y * 64, n0 = blockIdx.x * 64;

    // per-thread staging descriptors (8 chunks of the 2048-element tile)
    uint32_t adst[8], bdst[8];
    const float* asrcp[8];
    const float* bsrcp[8];
    bool bok[8];
#pragma unroll
    for (int j = 0; j < 8; j++) {
        int idx = threadIdx.x + j * 256;
        int mm = idx >> 5, kk = idx & 31;
        adst[j] = (uint32_t)((kk * 66 + mm) * 4);
        bdst[j] = (uint32_t)((mm * 33 + kk) * 4);
        asrcp[j] = A + (size_t)(m0 + mm) * K + kk;
        bsrcp[j] = W + (size_t)(n0 + mm) * K + kk;
        bok[j] = (n0 + mm < N);
        if (!bok[j]) { Bs[0][mm][kk] = 0.f; Bs[1][mm][kk] = 0.f; }
    }

    // prologue: stage k-tile 0 into buffer 0
#pragma unroll
    for (int j = 0; j < 8; j++) {
        cp4(as_b + adst[j], asrcp[j]);
        if (bok[j]) cp4(bs_b + bdst[j], bsrcp[j]);
    }
    cp_commit();

    float2 acc[2][4];
#pragma unroll
    for (int p = 0; p < 2; p++)
#pragma unroll
        for (int j = 0; j < 4; j++) acc[p][j] = make_float2(0.f, 0.f);

    int T = K >> 5;
    for (int kt = 0; kt < T; kt++) {
        cp_wait0();
        __syncthreads();
        if (kt + 1 < T) {
            int nb = (kt + 1) & 1;
            uint32_t ao = as_b + nb * AS_SZ, bo = bs_b + nb * BS_SZ;
            int koff = (kt + 1) * 32;
#pragma unroll
            for (int j = 0; j < 8; j++) {
                cp4(ao + adst[j], asrcp[j] + koff);
                if (bok[j]) cp4(bo + bdst[j], bsrcp[j] + koff);
            }
            cp_commit();
        }
        int cb = kt & 1;
#pragma unroll
        for (int kk = 0; kk < 32; kk++) {
            float2 a0 = *(const float2*)&As[cb][kk][ty * 4];
            float2 a1 = *(const float2*)&As[cb][kk][ty * 4 + 2];
#pragma unroll
            for (int j = 0; j < 4; j++) {
                float bv = Bs[cb][tx * 4 + j][kk];
                float2 b2 = make_float2(bv, bv);
                ffma2(acc[0][j], a0, b2);
                ffma2(acc[1][j], a1, b2);
            }
        }
    }
#pragma unroll
    for (int p = 0; p < 2; p++) {
        int cm0 = m0 + ty * 4 + p * 2;
#pragma unroll
        for (int j = 0; j < 4; j++) {
            int cn = n0 + tx * 4 + j;
            if (cn < N) {
                float bv = bias[cn];
                float v0 = acc[p][j].x + bv;
                float v1 = acc[p][j].y + bv;
                v0 = act ? (1.f / (1.f + expf(-v0))) : fmaxf(v0, 0.f);
                v1 = act ? (1.f / (1.f + expf(-v1))) : fmaxf(v1, 0.f);
                C[(size_t)cm0 * N + cn] = v0;
                C[(size_t)(cm0 + 1) * N + cn] = v1;
            }
        }
    }
}

extern "C" void kernel_launch(void* const* d_in, const int* in_sizes, int n_in,
                              void* d_out, int out_size) {
    const float* x   = (const float*)d_in[0];
    const float* c1w = (const float*)d_in[1];
    const float* c1b = (const float*)d_in[2];
    const float* pw  = (const float*)d_in[3];
    const float* pb  = (const float*)d_in[4];
    const float* rw  = (const float*)d_in[5];
    const float* w1  = (const float*)d_in[6];
    const float* b1  = (const float*)d_in[7];
    const float* w2  = (const float*)d_in[8];
    const float* b2  = (const float*)d_in[9];
    const float* w3  = (const float*)d_in[10];
    const float* b3  = (const float*)d_in[11];
    float* out = (float*)d_out;
    float* out_classes = out;              // [512,10]
    float* out_recon   = out + 512 * NC;   // [512,784]

    void *p_d1, *p_d2;
    cudaGetSymbolAddress(&p_d1, g_d1);
    cudaGetSymbolAddress(&p_d2, g_d2);

    prep_kernel<<<1696, 256>>>(pw, rw);                 // launch 1
    conv1_kernel<<<dim3(8, 256), 640>>>(x, c1w, c1b);   // launch 2

    int c2sm = 2 * C2_BUFSZ;  // 218112 B
    cudaFuncSetAttribute(conv2_mma_kernel, cudaFuncAttributeMaxDynamicSharedMemorySize, c2sm);
    conv2_mma_kernel<<<128, 512, c2sm>>>(pb);           // launch 3

    routing_kernel<<<dim3(512, 10), 288>>>();           // launch 4 (profiled slot)

    classes_kernel<<<512, 32>>>(out_classes);

    gemm1s_kernel<<<1024, 256>>>(w1, b1, (float*)p_d1);
    gemm_kernel<<<dim3(16, 8), 256>>>((const float*)p_d1, w2, b2, (float*)p_d2, 1024, 512, 0);
    gemm_kernel<<<dim3(13, 8), 256>>>((const float*)p_d2, w3, b3, out_recon, 784, 1024, 1);
}